// round 2
// baseline (speedup 1.0000x reference)
#include <cuda_runtime.h>
#include <math.h>
#include <stdint.h>

#define NMAX 32768
#define ETOT 262144
#define BGR  32
#define INVC 0.08838834764831845f   /* 1/sqrt(128) */

/* ------------------------------------------------------------------ */
/* Static scratch (no allocations allowed)                              */
/* ------------------------------------------------------------------ */
__device__ float g_xl [NMAX*128];
__device__ float g_q  [NMAX*512];
__device__ float g_k  [NMAX*512];
__device__ float g_v  [NMAX*512];
__device__ float g_o  [NMAX*512];
__device__ float g_P  [NMAX*256];
__device__ float g_qeb[NMAX*4];
__device__ float g_T  [NMAX*256];
__device__ float g_ex [ETOT*4];
__device__ float g_hA [NMAX*128];
__device__ float g_hB [NMAX*128];
__device__ float g_h1 [NMAX*128];
__device__ float g_dis[NMAX];
__device__ int   g_deg[NMAX];
__device__ int   g_cnt[NMAX];
__device__ int   g_fil[NMAX];
__device__ int   g_off[NMAX+1];
__device__ int   g_eid[ETOT];
__device__ int   g_ero[ETOT];
__device__ int   g_row[ETOT];
__device__ int   g_col[ETOT];
__device__ float g_ewc[ETOT];
__device__ int   g_keep[ETOT];
__device__ float g_bns[128];
__device__ float g_bnq[128];
__device__ float g_bsc[128];
__device__ float g_bsh[128];
__device__ float g_wn[1];
__device__ float g_sc  [NMAX];
__device__ float g_vals[NMAX];
__device__ int   g_perm[NMAX];
__device__ int   g_nid [NMAX];
__device__ float g_rep0[BGR*256];
__device__ float g_rep1[BGR*256];

/* ------------------------------------------------------------------ */
/* Generic fp32 GEMM:  C = op( A(MxK,lda) @ B(KxN,ldb) + bias )         */
/* flags: 1 = relu, 2 = accumulate into existing C                      */
/* M%64==0, N%64==0, K%16==0                                            */
/* ------------------------------------------------------------------ */
__global__ void sgemm(const float* __restrict__ A, int lda,
                      const float* __restrict__ B, int ldb,
                      const float* __restrict__ bias,
                      float* __restrict__ C, int ldc,
                      int M, int N, int K, int flags)
{
    __shared__ float As[16][68];
    __shared__ float Bs[16][68];
    int bm = blockIdx.y << 6, bn = blockIdx.x << 6;
    int t  = threadIdx.x;
    int ty = t >> 4, tx = t & 15;
    int ty4 = ty << 2, tx4 = tx << 2;
    float acc[4][4] = {};
    for (int k0 = 0; k0 < K; k0 += 16) {
#pragma unroll
        for (int i = 0; i < 4; i++) {
            int idx = t + (i << 8);
            int r  = idx >> 4, kk = idx & 15;
            As[kk][r] = A[(size_t)(bm + r) * lda + k0 + kk];
            int kk2 = idx >> 6, c = idx & 63;
            Bs[kk2][c] = B[(size_t)(k0 + kk2) * ldb + bn + c];
        }
        __syncthreads();
#pragma unroll
        for (int kk = 0; kk < 16; kk++) {
            float a0 = As[kk][ty4+0], a1 = As[kk][ty4+1],
                  a2 = As[kk][ty4+2], a3 = As[kk][ty4+3];
            float b0 = Bs[kk][tx4+0], b1 = Bs[kk][tx4+1],
                  b2 = Bs[kk][tx4+2], b3 = Bs[kk][tx4+3];
            acc[0][0]+=a0*b0; acc[0][1]+=a0*b1; acc[0][2]+=a0*b2; acc[0][3]+=a0*b3;
            acc[1][0]+=a1*b0; acc[1][1]+=a1*b1; acc[1][2]+=a1*b2; acc[1][3]+=a1*b3;
            acc[2][0]+=a2*b0; acc[2][1]+=a2*b1; acc[2][2]+=a2*b2; acc[2][3]+=a2*b3;
            acc[3][0]+=a3*b0; acc[3][1]+=a3*b1; acc[3][2]+=a3*b2; acc[3][3]+=a3*b3;
        }
        __syncthreads();
    }
#pragma unroll
    for (int i = 0; i < 4; i++) {
        int r = bm + ty4 + i;
#pragma unroll
        for (int j = 0; j < 4; j++) {
            int c = bn + tx4 + j;
            float vv = acc[i][j];
            if (bias) vv += bias[c];
            if (flags & 2) vv += C[(size_t)r * ldc + c];
            if (flags & 1) vv = fmaxf(vv, 0.f);
            C[(size_t)r * ldc + c] = vv;
        }
    }
}

/* C(MxN,ldc) = A(MxK,lda) @ B(NxK,ldb)^T.  N%64==0, K%16==0            */
__global__ void sgemm_nt(const float* __restrict__ A, int lda,
                         const float* __restrict__ B, int ldb,
                         float* __restrict__ C, int ldc,
                         int M, int N, int K)
{
    __shared__ float As[16][68];
    __shared__ float Bs[16][68];
    int bm = blockIdx.y << 6, bn = blockIdx.x << 6;
    int t  = threadIdx.x;
    int ty = t >> 4, tx = t & 15;
    int ty4 = ty << 2, tx4 = tx << 2;
    float acc[4][4] = {};
    for (int k0 = 0; k0 < K; k0 += 16) {
#pragma unroll
        for (int i = 0; i < 4; i++) {
            int idx = t + (i << 8);
            int r  = idx >> 4, kk = idx & 15;
            As[kk][r] = A[(size_t)(bm + r) * lda + k0 + kk];
            Bs[kk][r] = B[(size_t)(bn + r) * ldb + k0 + kk];
        }
        __syncthreads();
#pragma unroll
        for (int kk = 0; kk < 16; kk++) {
            float a0 = As[kk][ty4+0], a1 = As[kk][ty4+1],
                  a2 = As[kk][ty4+2], a3 = As[kk][ty4+3];
            float b0 = Bs[kk][tx4+0], b1 = Bs[kk][tx4+1],
                  b2 = Bs[kk][tx4+2], b3 = Bs[kk][tx4+3];
            acc[0][0]+=a0*b0; acc[0][1]+=a0*b1; acc[0][2]+=a0*b2; acc[0][3]+=a0*b3;
            acc[1][0]+=a1*b0; acc[1][1]+=a1*b1; acc[1][2]+=a1*b2; acc[1][3]+=a1*b3;
            acc[2][0]+=a2*b0; acc[2][1]+=a2*b1; acc[2][2]+=a2*b2; acc[2][3]+=a2*b3;
            acc[3][0]+=a3*b0; acc[3][1]+=a3*b1; acc[3][2]+=a3*b2; acc[3][3]+=a3*b3;
        }
        __syncthreads();
    }
#pragma unroll
    for (int i = 0; i < 4; i++) {
        int r = bm + ty4 + i;
#pragma unroll
        for (int j = 0; j < 4; j++)
            C[(size_t)r * ldc + bn + tx4 + j] = acc[i][j];
    }
}

/* ------------------------------------------------------------------ */
/* Graph plumbing kernels                                               */
/* ------------------------------------------------------------------ */
__global__ void einit(const int* __restrict__ ei, const float* __restrict__ ew)
{
    int e = blockIdx.x * 256 + threadIdx.x;
    if (e < ETOT) {
        g_row[e] = ei[e];
        g_col[e] = ei[ETOT + e];
        g_ewc[e] = ew[e];
        g_keep[e] = 1;
    }
}

__global__ void zero3(int n)
{
    int i = blockIdx.x * 256 + threadIdx.x;
    if (i < n) { g_deg[i] = 0; g_cnt[i] = 0; g_fil[i] = 0; }
}

__global__ void degcnt()
{
    int e = blockIdx.x * 256 + threadIdx.x;
    if (e < ETOT && g_keep[e]) {
        atomicAdd(&g_deg[g_row[e]], 1);
        atomicAdd(&g_cnt[g_col[e]], 1);
    }
}

__global__ void disk(int n)
{
    int i = blockIdx.x * 256 + threadIdx.x;
    if (i < n) {
        int d = g_deg[i];
        g_dis[i] = d > 0 ? 1.0f / sqrtf((float)d) : 0.0f;
    }
}

__global__ void scan_excl(int n)
{
    __shared__ int part[1024];
    int t = threadIdx.x;
    int chunk = (n + 1023) >> 10;
    int s0 = t * chunk;
    int sum = 0;
    for (int i = 0; i < chunk; i++) {
        int idx = s0 + i;
        if (idx < n) sum += g_cnt[idx];
    }
    part[t] = sum;
    __syncthreads();
    for (int d = 1; d < 1024; d <<= 1) {
        int v = (t >= d) ? part[t - d] : 0;
        __syncthreads();
        part[t] += v;
        __syncthreads();
    }
    int run = (t == 0) ? 0 : part[t - 1];
    for (int i = 0; i < chunk; i++) {
        int idx = s0 + i;
        if (idx < n) { g_off[idx] = run; run += g_cnt[idx]; }
    }
    if (t == 1023) g_off[n] = part[1023];
}

__global__ void fillk()
{
    int e = blockIdx.x * 256 + threadIdx.x;
    if (e < ETOT && g_keep[e]) {
        int c = g_col[e];
        int p = g_off[c] + atomicAdd(&g_fil[c], 1);
        g_eid[p] = e;
        g_ero[p] = g_row[e];
    }
}

/* q . e_b per (node, head) */
__global__ void qeb_k(const float* __restrict__ ebias)
{
    int d = blockIdx.x;
    int h = threadIdx.x >> 5, lane = threadIdx.x & 31;
    float a = 0.f;
    const float* qr = g_q + (size_t)d * 512 + h * 128;
    const float* er = ebias + h * 128;
    for (int c = lane; c < 128; c += 32) a += qr[c] * er[c];
#pragma unroll
    for (int o = 16; o; o >>= 1) a += __shfl_xor_sync(~0u, a, o);
    if (lane == 0) g_qeb[d * 4 + h] = a;
}

/* ------------------------------------------------------------------ */
/* Main attention/aggregation kernel: one block (256 thr) per dst node */
/* ------------------------------------------------------------------ */
__global__ void node_kernel(const float* __restrict__ ea,
                            const float* __restrict__ ebias)
{
    int d   = blockIdx.x;
    int t   = threadIdx.x;
    int beg = g_off[d], deg = g_off[d + 1] - beg;
    if (deg == 0) { g_T[(size_t)d * 256 + t] = 0.f; return; }

    __shared__ float qs[512];
    __shared__ float Ps[256];
    __shared__ float sxw[128];
    __shared__ float wmax[8][4];
    __shared__ float hmax[4];
    __shared__ float den[4];

    qs[t]       = g_q[(size_t)d * 512 + t];
    qs[t + 256] = g_q[(size_t)d * 512 + 256 + t];
    Ps[t]       = g_P[(size_t)d * 256 + t];
    int w = t >> 5, lane = t & 31;
    if (lane == 0) { wmax[w][0] = wmax[w][1] = wmax[w][2] = wmax[w][3] = -3.4e38f; }
    if (t < 4) den[t] = 0.f;
    __syncthreads();

    float qe0 = g_qeb[d * 4 + 0], qe1 = g_qeb[d * 4 + 1],
          qe2 = g_qeb[d * 4 + 2], qe3 = g_qeb[d * 4 + 3];

    /* pass 1: alpha per edge (warp per edge) */
    float lm0 = -3.4e38f, lm1 = -3.4e38f, lm2 = -3.4e38f, lm3 = -3.4e38f;
    for (int j = w; j < deg; j += 8) {
        int slot = beg + j;
        int e    = g_eid[slot];
        int row  = g_ero[slot];
        const float* kr = g_k + (size_t)row * 512;
        float a0 = 0.f, a1 = 0.f, a2 = 0.f, a3 = 0.f;
        for (int c = lane; c < 128; c += 32) {
            a0 += qs[c]       * kr[c];
            a1 += qs[128 + c] * kr[128 + c];
            a2 += qs[256 + c] * kr[256 + c];
            a3 += qs[384 + c] * kr[384 + c];
        }
        const float* eae = ea + (size_t)e * 64;
        for (int f = lane; f < 64; f += 32) {
            float vv = eae[f];
            a0 += vv * Ps[f];
            a1 += vv * Ps[64 + f];
            a2 += vv * Ps[128 + f];
            a3 += vv * Ps[192 + f];
        }
#pragma unroll
        for (int o = 16; o; o >>= 1) {
            a0 += __shfl_xor_sync(~0u, a0, o);
            a1 += __shfl_xor_sync(~0u, a1, o);
            a2 += __shfl_xor_sync(~0u, a2, o);
            a3 += __shfl_xor_sync(~0u, a3, o);
        }
        if (lane == 0) {
            float al0 = (a0 + qe0) * INVC;
            float al1 = (a1 + qe1) * INVC;
            float al2 = (a2 + qe2) * INVC;
            float al3 = (a3 + qe3) * INVC;
            g_ex[(size_t)slot * 4 + 0] = al0;
            g_ex[(size_t)slot * 4 + 1] = al1;
            g_ex[(size_t)slot * 4 + 2] = al2;
            g_ex[(size_t)slot * 4 + 3] = al3;
            lm0 = fmaxf(lm0, al0); lm1 = fmaxf(lm1, al1);
            lm2 = fmaxf(lm2, al2); lm3 = fmaxf(lm3, al3);
        }
    }
    if (lane == 0) { wmax[w][0] = lm0; wmax[w][1] = lm1; wmax[w][2] = lm2; wmax[w][3] = lm3; }
    __syncthreads();
    if (t < 4) {
        float m = -3.4e38f;
        for (int ww = 0; ww < 8; ww++) m = fmaxf(m, wmax[ww][t]);
        hmax[t] = m;
    }
    __syncthreads();

    /* pass 1.5: exp + den */
    for (int t2 = t; t2 < deg * 4; t2 += 256) {
        int slot = beg + (t2 >> 2);
        int h    = t2 & 3;
        float ex = __expf(g_ex[(size_t)slot * 4 + h] - hmax[h]);
        g_ex[(size_t)slot * 4 + h] = ex;
        atomicAdd(&den[h], ex);
    }
    __syncthreads();

    /* pass 2: aggregate v, edge-attr moments, degree-norm branch */
    int   h0 = t >> 7, h1 = h0 + 2, hT = t >> 6;
    float agg0 = 0.f, agg1 = 0.f, Tc = 0.f, xwc = 0.f;
    float ddis = g_dis[d];
    for (int j = 0; j < deg; j++) {
        int slot = beg + j;
        int e    = g_eid[slot];
        int row  = g_ero[slot];
        float e0 = g_ex[(size_t)slot * 4 + h0];
        float e1 = g_ex[(size_t)slot * 4 + h1];
        float eT = g_ex[(size_t)slot * 4 + hT];
        const float* vr = g_v + (size_t)row * 512;
        agg0 += e0 * vr[t];
        agg1 += e1 * vr[256 + t];
        Tc   += eT * ea[(size_t)e * 64 + (t & 63)];
        if (t < 128)
            xwc += ddis * g_ewc[e] * g_dis[row] * g_xl[(size_t)row * 128 + t];
    }
    if (t < 128) sxw[t] = xwc;
    __syncthreads();

    float d0 = den[h0] + 1e-16f, d1 = den[h1] + 1e-16f, dT = den[hT] + 1e-16f;
    float s0 = den[h0] / d0,     s1 = den[h1] / d1;
    float xw = sxw[t & 127];
    g_o[(size_t)d * 512 + t]       += agg0 / d0 + s0 * ebias[t]       + xw;
    g_o[(size_t)d * 512 + 256 + t] += agg1 / d1 + s1 * ebias[256 + t] + xw;
    g_T[(size_t)d * 256 + t]        = Tc / dT;
}

/* ------------------------------------------------------------------ */
/* BatchNorm                                                            */
/* ------------------------------------------------------------------ */
__global__ void bnzero()
{
    int c = threadIdx.x;
    g_bns[c] = 0.f; g_bnq[c] = 0.f;
}

__global__ void bnstat(int n)
{
    int c  = threadIdx.x;
    int r0 = blockIdx.x * 128;
    float s = 0.f, q = 0.f;
    for (int r = 0; r < 128; r++) {
        float v = g_h1[(size_t)(r0 + r) * 128 + c];
        s += v; q += v * v;
    }
    atomicAdd(&g_bns[c], s);
    atomicAdd(&g_bnq[c], q);
}

__global__ void bnfin(const float* __restrict__ g, const float* __restrict__ b, int n)
{
    int c = threadIdx.x;
    float mu  = g_bns[c] / (float)n;
    float var = g_bnq[c] / (float)n - mu * mu;
    float sc  = g[c] * rsqrtf(var + 1e-5f);
    g_bsc[c] = sc;
    g_bsh[c] = b[c] - mu * sc;
}

__global__ void bnapply(float* __restrict__ out, int n)
{
    int i = blockIdx.x * 256 + threadIdx.x;
    if (i < n * 128) {
        int c = i & 127;
        out[i] = g_h1[i] * g_bsc[c] + g_bsh[c];
    }
}

/* ------------------------------------------------------------------ */
/* Top-k pooling                                                        */
/* ------------------------------------------------------------------ */
__global__ void wnorm_k(const float* __restrict__ w)
{
    __shared__ float s[128];
    int t = threadIdx.x;
    s[t] = w[t] * w[t];
    __syncthreads();
    for (int o = 64; o; o >>= 1) {
        if (t < o) s[t] += s[t + o];
        __syncthreads();
    }
    if (t == 0) g_wn[0] = sqrtf(s[0]) + 1e-16f;
}

__global__ void score_k(const float* __restrict__ h, const float* __restrict__ w, int n)
{
    int warp = (blockIdx.x * blockDim.x + threadIdx.x) >> 5;
    int lane = threadIdx.x & 31;
    if (warp >= n) return;
    float a = 0.f;
    const float* hr = h + (size_t)warp * 128;
    for (int c = lane; c < 128; c += 32) a += hr[c] * w[c];
#pragma unroll
    for (int o = 16; o; o >>= 1) a += __shfl_xor_sync(~0u, a, o);
    if (lane == 0) g_sc[warp] = tanhf(a / g_wn[0]);
}

__global__ void nidinit(int n)
{
    int i = blockIdx.x * 256 + threadIdx.x;
    if (i < n) g_nid[i] = -1;
}

/* one block per graph; threads == n_per (pow2 <= 1024). Bitonic sort:
   descending by value, ascending index on ties (matches jax top_k). */
__global__ void topk_pool(int n_per, int kk)
{
    __shared__ float sv[1024];
    __shared__ int   si[1024];
    int b = blockIdx.x, t = threadIdx.x;
    sv[t] = g_sc[b * n_per + t];
    si[t] = t;
    __syncthreads();
    for (int k2 = 2; k2 <= n_per; k2 <<= 1) {
        for (int j = k2 >> 1; j > 0; j >>= 1) {
            int ixj = t ^ j;
            if (ixj > t) {
                bool up = ((t & k2) == 0);
                float va = sv[t], vb = sv[ixj];
                int   ia = si[t], ib = si[ixj];
                bool aFirst = (va > vb) || (va == vb && ia < ib);
                if (up ? !aFirst : aFirst) {
                    sv[t] = vb; sv[ixj] = va;
                    si[t] = ib; si[ixj] = ia;
                }
            }
            __syncthreads();
        }
    }
    if (t < kk) {
        int gi = b * n_per + si[t];
        int r  = b * kk + t;
        g_vals[r] = sv[t];
        g_perm[r] = gi;
        g_nid[gi] = r;
    }
}

__global__ void gather_k(const float* __restrict__ hin, float* __restrict__ hout, int n_new)
{
    int i = blockIdx.x * 256 + threadIdx.x;
    if (i < n_new * 128) {
        int r = i >> 7, c = i & 127;
        hout[i] = hin[(size_t)g_perm[r] * 128 + c] * g_vals[r];
    }
}

__global__ void remap_k()
{
    int e = blockIdx.x * 256 + threadIdx.x;
    if (e < ETOT && g_keep[e]) {
        int nr = g_nid[g_row[e]], nc = g_nid[g_col[e]];
        if (nr >= 0 && nc >= 0) { g_row[e] = nr; g_col[e] = nc; }
        else { g_keep[e] = 0; g_row[e] = 0; g_col[e] = 0; g_ewc[e] = 0.f; }
    }
}

__global__ void reps_k(const float* __restrict__ h, int n_per, int which)
{
    int b = blockIdx.x, c = threadIdx.x;
    float mx = -3.4e38f, sm = 0.f;
    for (int r = 0; r < n_per; r++) {
        float v = h[(size_t)(b * n_per + r) * 128 + c];
        mx = fmaxf(mx, v);
        sm += v;
    }
    float* rep = which ? g_rep1 : g_rep0;
    rep[b * 256 + c]       = mx;
    rep[b * 256 + 128 + c] = sm / (float)n_per;
}

__global__ void add_rep(float* __restrict__ out)
{
    int i = blockIdx.x * 256 + threadIdx.x;
    if (i < BGR * 256) out[i] = g_rep0[i] + g_rep1[i];
}

/* ------------------------------------------------------------------ */
/* Host orchestration                                                   */
/* ------------------------------------------------------------------ */
extern "C" void kernel_launch(void* const* d_in, const int* in_sizes, int n_in,
                              void* d_out, int out_size)
{
    const float* x        = (const float*)d_in[0];
    const float* ea       = (const float*)d_in[1];
    const int*   ei       = (const int*)  d_in[2];
    const float* ew_in    = (const float*)d_in[3];
    const float* lin0_w   = (const float*)d_in[5];
    const float* lin0_b   = (const float*)d_in[6];
    const float* lin_w    = (const float*)d_in[7];
    const float* lin_b    = (const float*)d_in[8];
    const float* q_w      = (const float*)d_in[9];
    const float* q_b      = (const float*)d_in[10];
    const float* k_w      = (const float*)d_in[11];
    const float* k_b      = (const float*)d_in[12];
    const float* v_w      = (const float*)d_in[13];
    const float* v_b      = (const float*)d_in[14];
    const float* e_w      = (const float*)d_in[15];
    const float* e_b      = (const float*)d_in[16];
    const float* s_w      = (const float*)d_in[17];
    const float* s_b      = (const float*)d_in[18];
    const float* tr_w     = (const float*)d_in[19];
    const float* tr_b     = (const float*)d_in[20];
    const float* bn_g     = (const float*)d_in[21];
    const float* bn_b     = (const float*)d_in[22];
    const float* pool_w   = (const float*)d_in[23];
    float*       out      = (float*)d_out;

    float *p_xl, *p_q, *p_k, *p_v, *p_o, *p_P, *p_T, *p_h1, *p_hA, *p_hB;
    cudaGetSymbolAddress((void**)&p_xl, g_xl);
    cudaGetSymbolAddress((void**)&p_q,  g_q);
    cudaGetSymbolAddress((void**)&p_k,  g_k);
    cudaGetSymbolAddress((void**)&p_v,  g_v);
    cudaGetSymbolAddress((void**)&p_o,  g_o);
    cudaGetSymbolAddress((void**)&p_P,  g_P);
    cudaGetSymbolAddress((void**)&p_T,  g_T);
    cudaGetSymbolAddress((void**)&p_h1, g_h1);
    cudaGetSymbolAddress((void**)&p_hA, g_hA);
    cudaGetSymbolAddress((void**)&p_hB, g_hB);

    const int EB = (ETOT + 255) / 256;

    /* edge state init (must run every call: graph replays mutate it) */
    einit<<<EB, 256>>>(ei, ew_in);

    auto run_layer = [&](const float* hin, int inF, int n,
                         const float* lw, const float* lb, int L, float* hout)
    {
        const float* qw  = q_w  + (size_t)L * 128 * 512;
        const float* qb  = q_b  + (size_t)L * 512;
        const float* kw  = k_w  + (size_t)L * 128 * 512;
        const float* kb  = k_b  + (size_t)L * 512;
        const float* vw  = v_w  + (size_t)L * 128 * 512;
        const float* vb  = v_b  + (size_t)L * 512;
        const float* eww = e_w  + (size_t)L * 64 * 512;
        const float* ebb = e_b  + (size_t)L * 512;
        const float* sw  = s_w  + (size_t)L * 128 * 512;
        const float* sb  = s_b  + (size_t)L * 512;
        const float* trw = tr_w + (size_t)L * 512 * 128;
        const float* trb = tr_b + (size_t)L * 128;
        const float* bg  = bn_g + (size_t)L * 128;
        const float* bb  = bn_b + (size_t)L * 128;

        /* xl = hin @ lw + lb */
        sgemm<<<dim3(2, n / 64), 256>>>(hin, inF, lw, 128, lb, p_xl, 128, n, 128, inF, 0);
        /* q, k, v, skip */
        sgemm<<<dim3(8, n / 64), 256>>>(p_xl, 128, qw, 512, qb, p_q, 512, n, 512, 128, 0);
        sgemm<<<dim3(8, n / 64), 256>>>(p_xl, 128, kw, 512, kb, p_k, 512, n, 512, 128, 0);
        sgemm<<<dim3(8, n / 64), 256>>>(p_xl, 128, vw, 512, vb, p_v, 512, n, 512, 128, 0);
        sgemm<<<dim3(8, n / 64), 256>>>(p_xl, 128, sw, 512, sb, p_o, 512, n, 512, 128, 0);
        /* P[n,h,64] = q_h @ e_w_h^T per head */
        for (int h = 0; h < 4; h++)
            sgemm_nt<<<dim3(1, n / 64), 256>>>(p_q + h * 128, 512,
                                               eww + h * 128, 512,
                                               p_P + h * 64, 256, n, 64, 128);
        qeb_k<<<n, 128>>>(ebb);

        /* degree + CSR */
        zero3<<<(n + 255) / 256, 256>>>(n);
        degcnt<<<EB, 256>>>();
        disk<<<(n + 255) / 256, 256>>>(n);
        scan_excl<<<1, 1024>>>(n);
        fillk<<<EB, 256>>>();

        /* attention + aggregation */
        node_kernel<<<n, 256>>>(ea, ebb);

        /* out += T @ e_w (block-diag per head) */
        for (int h = 0; h < 4; h++)
            sgemm<<<dim3(2, n / 64), 256>>>(p_T + h * 64, 256,
                                            eww + h * 128, 512, nullptr,
                                            p_o + h * 128, 512, n, 128, 64, 2);

        /* h1 = relu(out @ tr_w + tr_b) ; bn */
        sgemm<<<dim3(2, n / 64), 256>>>(p_o, 512, trw, 128, trb, p_h1, 128, n, 128, 512, 1);
        bnzero<<<1, 128>>>();
        bnstat<<<n / 128, 128>>>(n);
        bnfin<<<1, 128>>>(bg, bb, n);
        bnapply<<<(n * 128 + 255) / 256, 256>>>(hout, n);
    };

    auto do_pool = [&](const float* hin, float* hout, int n_old, int n_per,
                       const float* w, int which)
    {
        int kk    = n_per / 2;
        int n_new = BGR * kk;
        wnorm_k<<<1, 128>>>(w);
        score_k<<<n_old / 8, 256>>>(hin, w, n_old);
        nidinit<<<(n_old + 255) / 256, 256>>>(n_old);
        topk_pool<<<BGR, n_per>>>(n_per, kk);
        gather_k<<<(n_new * 128 + 255) / 256, 256>>>(hin, hout, n_new);
        remap_k<<<EB, 256>>>();
        reps_k<<<BGR, 128>>>(hout, kk, which);
    };

    /* layer 0 */
    run_layer(x, 256, 32768, lin0_w, lin0_b, 0, p_hA);
    /* layer 1 + pool 1 */
    run_layer(p_hA, 128, 32768, lin_w + 0 * 128 * 128, lin_b + 0 * 128, 1, p_hB);
    do_pool(p_hB, p_hA, 32768, 1024, pool_w, 0);
    /* layer 2 (no pool) */
    run_layer(p_hA, 128, 16384, lin_w + 1 * 128 * 128, lin_b + 1 * 128, 2, p_hB);
    /* layer 3 + pool 2 */
    run_layer(p_hB, 128, 16384, lin_w + 2 * 128 * 128, lin_b + 2 * 128, 3, p_hA);
    do_pool(p_hA, p_hB, 16384, 512, pool_w + 128, 1);

    add_rep<<<32, 256>>>(out);
}

// round 3
// speedup vs baseline: 1.1807x; 1.1807x over previous
#include <cuda_runtime.h>
#include <math.h>
#include <stdint.h>

#define NMAX 32768
#define ETOT 262144
#define BGR  32
#define INVC 0.08838834764831845f   /* 1/sqrt(128) */

/* ------------------------------------------------------------------ */
/* Static scratch (no allocations allowed)                              */
/* ------------------------------------------------------------------ */
__device__ float g_xl [NMAX*128];
__device__ float g_q  [NMAX*512];
__device__ float g_k  [NMAX*512];
__device__ float g_v  [NMAX*512];
__device__ float g_o  [NMAX*512];
__device__ float g_P  [NMAX*256];
__device__ float g_qeb[NMAX*4];
__device__ float g_T  [NMAX*256];
__device__ float g_ex [ETOT*4];
__device__ float g_hA [NMAX*128];
__device__ float g_hB [NMAX*128];
__device__ float g_h1 [NMAX*128];
__device__ float g_dis[NMAX];
__device__ int   g_deg[NMAX];
__device__ int   g_cnt[NMAX];
__device__ int   g_fil[NMAX];
__device__ int   g_off[NMAX+1];
__device__ int   g_eid[ETOT];
__device__ int   g_ero[ETOT];
__device__ int   g_row[ETOT];
__device__ int   g_col[ETOT];
__device__ float g_ewc[ETOT];
__device__ int   g_keep[ETOT];
__device__ float g_bns[128];
__device__ float g_bnq[128];
__device__ float g_bsc[128];
__device__ float g_bsh[128];
__device__ float g_wn[1];
__device__ float g_sc  [NMAX];
__device__ float g_vals[NMAX];
__device__ int   g_perm[NMAX];
__device__ int   g_nid [NMAX];
__device__ float g_rep0[BGR*256];
__device__ float g_rep1[BGR*256];

/* ------------------------------------------------------------------ */
/* packed fp32x2 helpers (sm_103a FFMA2 — only reachable via PTX)       */
/* ------------------------------------------------------------------ */
__device__ __forceinline__ unsigned long long pk2(float lo, float hi)
{
    unsigned long long r;
    asm("mov.b64 %0, {%1, %2};" : "=l"(r) : "f"(lo), "f"(hi));
    return r;
}
__device__ __forceinline__ void upk2(unsigned long long v, float& lo, float& hi)
{
    asm("mov.b64 {%0, %1}, %2;" : "=f"(lo), "=f"(hi) : "l"(v));
}
__device__ __forceinline__ unsigned long long ffma2(unsigned long long a,
                                                    unsigned long long b,
                                                    unsigned long long c)
{
    unsigned long long d;
    asm("fma.rn.f32x2 %0, %1, %2, %3;" : "=l"(d) : "l"(a), "l"(b), "l"(c));
    return d;
}

/* ------------------------------------------------------------------ */
/* fp32 GEMM, 128x128 tile, 8x8 microtile, FFMA2 inner loop.            */
/* C = op( A(MxK,lda) @ B(KxN,ldb) + bias ), per-z pointer strides.     */
/* flags: 1 = relu, 2 = accumulate into existing C.                     */
/* M%128==0, N%128==0, K%8==0, all pointers 16B-aligned.                */
/* ------------------------------------------------------------------ */
__global__ void __launch_bounds__(256, 2)
sgemm128(const float* __restrict__ A, int lda, long az,
         const float* __restrict__ B, int ldb, long bz,
         const float* __restrict__ bias,
         float* __restrict__ C, int ldc, long cz,
         int K, int flags)
{
    A += (long)blockIdx.z * az;
    B += (long)blockIdx.z * bz;
    C += (long)blockIdx.z * cz;

    __shared__ float As[8][128];
    __shared__ float Bs[8][128];

    int bm = blockIdx.y << 7, bn = blockIdx.x << 7;
    int t  = threadIdx.x;
    int ty = t >> 4, tx = t & 15;
    int ra = ty << 2, cb = tx << 2;

    /* global-load mapping */
    int arow = t >> 1;            /* 0..127 */
    int akc  = (t & 1) << 2;      /* 0 or 4 */
    int brow = t >> 5;            /* 0..7   */
    int bcol = (t & 31) << 2;     /* 0..124 */

    unsigned long long acc2[8][4];
#pragma unroll
    for (int i = 0; i < 8; i++)
#pragma unroll
        for (int j = 0; j < 4; j++) acc2[i][j] = 0ull;

    for (int k0 = 0; k0 < K; k0 += 8) {
        float4 av = *(const float4*)&A[(size_t)(bm + arow) * lda + k0 + akc];
        float4 bv = *(const float4*)&B[(size_t)(k0 + brow) * ldb + bn + bcol];
        As[akc + 0][arow] = av.x;
        As[akc + 1][arow] = av.y;
        As[akc + 2][arow] = av.z;
        As[akc + 3][arow] = av.w;
        *(float4*)&Bs[brow][bcol] = bv;
        __syncthreads();
#pragma unroll
        for (int kk = 0; kk < 8; kk++) {
            float4 a0 = *(float4*)&As[kk][ra];
            float4 a1 = *(float4*)&As[kk][64 + ra];
            float4 b0 = *(float4*)&Bs[kk][cb];
            float4 b1 = *(float4*)&Bs[kk][64 + cb];
            unsigned long long bp[4] = { pk2(b0.x, b0.y), pk2(b0.z, b0.w),
                                         pk2(b1.x, b1.y), pk2(b1.z, b1.w) };
            float a[8] = { a0.x, a0.y, a0.z, a0.w, a1.x, a1.y, a1.z, a1.w };
#pragma unroll
            for (int i = 0; i < 8; i++) {
                unsigned long long ap = pk2(a[i], a[i]);
#pragma unroll
                for (int j = 0; j < 4; j++)
                    acc2[i][j] = ffma2(ap, bp[j], acc2[i][j]);
            }
        }
        __syncthreads();
    }

    /* epilogue */
#pragma unroll
    for (int i = 0; i < 8; i++) {
        int r = bm + ((i < 4) ? (ra + i) : (64 + ra + i - 4));
#pragma unroll
        for (int g = 0; g < 2; g++) {
            int c = bn + (g ? 64 + cb : cb);
            float v0, v1, v2, v3;
            upk2(acc2[i][g * 2 + 0], v0, v1);
            upk2(acc2[i][g * 2 + 1], v2, v3);
            if (bias) {
                float4 bb = *(const float4*)&bias[c];
                v0 += bb.x; v1 += bb.y; v2 += bb.z; v3 += bb.w;
            }
            float* cp = &C[(size_t)r * ldc + c];
            if (flags & 2) {
                float4 old = *(float4*)cp;
                v0 += old.x; v1 += old.y; v2 += old.z; v3 += old.w;
            }
            if (flags & 1) {
                v0 = fmaxf(v0, 0.f); v1 = fmaxf(v1, 0.f);
                v2 = fmaxf(v2, 0.f); v3 = fmaxf(v3, 0.f);
            }
            float4 res = { v0, v1, v2, v3 };
            *(float4*)cp = res;
        }
    }
}

/* C(MxN,ldc) = A(MxK,lda) @ B(NxK,ldb)^T, per-z strides. N%64, K%16.   */
__global__ void sgemm_nt(const float* __restrict__ A, int lda, long az,
                         const float* __restrict__ B, int ldb, long bz,
                         float* __restrict__ C, int ldc, long cz,
                         int K)
{
    A += (long)blockIdx.z * az;
    B += (long)blockIdx.z * bz;
    C += (long)blockIdx.z * cz;
    __shared__ float As[16][68];
    __shared__ float Bs[16][68];
    int bm = blockIdx.y << 6, bn = blockIdx.x << 6;
    int t  = threadIdx.x;
    int ty = t >> 4, tx = t & 15;
    int ty4 = ty << 2, tx4 = tx << 2;
    float acc[4][4] = {};
    for (int k0 = 0; k0 < K; k0 += 16) {
#pragma unroll
        for (int i = 0; i < 4; i++) {
            int idx = t + (i << 8);
            int r  = idx >> 4, kk = idx & 15;
            As[kk][r] = A[(size_t)(bm + r) * lda + k0 + kk];
            Bs[kk][r] = B[(size_t)(bn + r) * ldb + k0 + kk];
        }
        __syncthreads();
#pragma unroll
        for (int kk = 0; kk < 16; kk++) {
            float a0 = As[kk][ty4+0], a1 = As[kk][ty4+1],
                  a2 = As[kk][ty4+2], a3 = As[kk][ty4+3];
            float b0 = Bs[kk][tx4+0], b1 = Bs[kk][tx4+1],
                  b2 = Bs[kk][tx4+2], b3 = Bs[kk][tx4+3];
            acc[0][0]+=a0*b0; acc[0][1]+=a0*b1; acc[0][2]+=a0*b2; acc[0][3]+=a0*b3;
            acc[1][0]+=a1*b0; acc[1][1]+=a1*b1; acc[1][2]+=a1*b2; acc[1][3]+=a1*b3;
            acc[2][0]+=a2*b0; acc[2][1]+=a2*b1; acc[2][2]+=a2*b2; acc[2][3]+=a2*b3;
            acc[3][0]+=a3*b0; acc[3][1]+=a3*b1; acc[3][2]+=a3*b2; acc[3][3]+=a3*b3;
        }
        __syncthreads();
    }
#pragma unroll
    for (int i = 0; i < 4; i++) {
        int r = bm + ty4 + i;
#pragma unroll
        for (int j = 0; j < 4; j++)
            C[(size_t)r * ldc + bn + tx4 + j] = acc[i][j];
    }
}

/* ------------------------------------------------------------------ */
/* Graph plumbing kernels                                               */
/* ------------------------------------------------------------------ */
__global__ void einit(const int* __restrict__ ei, const float* __restrict__ ew)
{
    int e = blockIdx.x * 256 + threadIdx.x;
    if (e < ETOT) {
        g_row[e] = ei[e];
        g_col[e] = ei[ETOT + e];
        g_ewc[e] = ew[e];
        g_keep[e] = 1;
    }
}

__global__ void zero3(int n)
{
    int i = blockIdx.x * 256 + threadIdx.x;
    if (i < n) { g_deg[i] = 0; g_cnt[i] = 0; g_fil[i] = 0; }
}

__global__ void degcnt()
{
    int e = blockIdx.x * 256 + threadIdx.x;
    if (e < ETOT && g_keep[e]) {
        atomicAdd(&g_deg[g_row[e]], 1);
        atomicAdd(&g_cnt[g_col[e]], 1);
    }
}

__global__ void disk(int n)
{
    int i = blockIdx.x * 256 + threadIdx.x;
    if (i < n) {
        int d = g_deg[i];
        g_dis[i] = d > 0 ? 1.0f / sqrtf((float)d) : 0.0f;
    }
}

__global__ void scan_excl(int n)
{
    __shared__ int part[1024];
    int t = threadIdx.x;
    int chunk = (n + 1023) >> 10;
    int s0 = t * chunk;
    int sum = 0;
    for (int i = 0; i < chunk; i++) {
        int idx = s0 + i;
        if (idx < n) sum += g_cnt[idx];
    }
    part[t] = sum;
    __syncthreads();
    for (int d = 1; d < 1024; d <<= 1) {
        int v = (t >= d) ? part[t - d] : 0;
        __syncthreads();
        part[t] += v;
        __syncthreads();
    }
    int run = (t == 0) ? 0 : part[t - 1];
    for (int i = 0; i < chunk; i++) {
        int idx = s0 + i;
        if (idx < n) { g_off[idx] = run; run += g_cnt[idx]; }
    }
    if (t == 1023) g_off[n] = part[1023];
}

__global__ void fillk()
{
    int e = blockIdx.x * 256 + threadIdx.x;
    if (e < ETOT && g_keep[e]) {
        int c = g_col[e];
        int p = g_off[c] + atomicAdd(&g_fil[c], 1);
        g_eid[p] = e;
        g_ero[p] = g_row[e];
    }
}

/* q . e_b per (node, head) */
__global__ void qeb_k(const float* __restrict__ ebias)
{
    int d = blockIdx.x;
    int h = threadIdx.x >> 5, lane = threadIdx.x & 31;
    float a = 0.f;
    const float* qr = g_q + (size_t)d * 512 + h * 128;
    const float* er = ebias + h * 128;
    for (int c = lane; c < 128; c += 32) a += qr[c] * er[c];
#pragma unroll
    for (int o = 16; o; o >>= 1) a += __shfl_xor_sync(~0u, a, o);
    if (lane == 0) g_qeb[d * 4 + h] = a;
}

/* ------------------------------------------------------------------ */
/* Main attention/aggregation kernel: one block (256 thr) per dst node */
/* ------------------------------------------------------------------ */
__global__ void node_kernel(const float* __restrict__ ea,
                            const float* __restrict__ ebias)
{
    int d   = blockIdx.x;
    int t   = threadIdx.x;
    int beg = g_off[d], deg = g_off[d + 1] - beg;
    if (deg == 0) { g_T[(size_t)d * 256 + t] = 0.f; return; }

    __shared__ float qs[512];
    __shared__ float Ps[256];
    __shared__ float sxw[128];
    __shared__ float wmax[8][4];
    __shared__ float hmax[4];
    __shared__ float den[4];

    qs[t]       = g_q[(size_t)d * 512 + t];
    qs[t + 256] = g_q[(size_t)d * 512 + 256 + t];
    Ps[t]       = g_P[(size_t)d * 256 + t];
    int w = t >> 5, lane = t & 31;
    if (lane == 0) { wmax[w][0] = wmax[w][1] = wmax[w][2] = wmax[w][3] = -3.4e38f; }
    if (t < 4) den[t] = 0.f;
    __syncthreads();

    float qe0 = g_qeb[d * 4 + 0], qe1 = g_qeb[d * 4 + 1],
          qe2 = g_qeb[d * 4 + 2], qe3 = g_qeb[d * 4 + 3];

    /* pass 1: alpha per edge (warp per edge) */
    float lm0 = -3.4e38f, lm1 = -3.4e38f, lm2 = -3.4e38f, lm3 = -3.4e38f;
    for (int j = w; j < deg; j += 8) {
        int slot = beg + j;
        int e    = g_eid[slot];
        int row  = g_ero[slot];
        const float* kr = g_k + (size_t)row * 512;
        float a0 = 0.f, a1 = 0.f, a2 = 0.f, a3 = 0.f;
        for (int c = lane; c < 128; c += 32) {
            a0 += qs[c]       * kr[c];
            a1 += qs[128 + c] * kr[128 + c];
            a2 += qs[256 + c] * kr[256 + c];
            a3 += qs[384 + c] * kr[384 + c];
        }
        const float* eae = ea + (size_t)e * 64;
        for (int f = lane; f < 64; f += 32) {
            float vv = eae[f];
            a0 += vv * Ps[f];
            a1 += vv * Ps[64 + f];
            a2 += vv * Ps[128 + f];
            a3 += vv * Ps[192 + f];
        }
#pragma unroll
        for (int o = 16; o; o >>= 1) {
            a0 += __shfl_xor_sync(~0u, a0, o);
            a1 += __shfl_xor_sync(~0u, a1, o);
            a2 += __shfl_xor_sync(~0u, a2, o);
            a3 += __shfl_xor_sync(~0u, a3, o);
        }
        if (lane == 0) {
            float al0 = (a0 + qe0) * INVC;
            float al1 = (a1 + qe1) * INVC;
            float al2 = (a2 + qe2) * INVC;
            float al3 = (a3 + qe3) * INVC;
            g_ex[(size_t)slot * 4 + 0] = al0;
            g_ex[(size_t)slot * 4 + 1] = al1;
            g_ex[(size_t)slot * 4 + 2] = al2;
            g_ex[(size_t)slot * 4 + 3] = al3;
            lm0 = fmaxf(lm0, al0); lm1 = fmaxf(lm1, al1);
            lm2 = fmaxf(lm2, al2); lm3 = fmaxf(lm3, al3);
        }
    }
    if (lane == 0) { wmax[w][0] = lm0; wmax[w][1] = lm1; wmax[w][2] = lm2; wmax[w][3] = lm3; }
    __syncthreads();
    if (t < 4) {
        float m = -3.4e38f;
        for (int ww = 0; ww < 8; ww++) m = fmaxf(m, wmax[ww][t]);
        hmax[t] = m;
    }
    __syncthreads();

    /* pass 1.5: exp + den */
    for (int t2 = t; t2 < deg * 4; t2 += 256) {
        int slot = beg + (t2 >> 2);
        int h    = t2 & 3;
        float ex = __expf(g_ex[(size_t)slot * 4 + h] - hmax[h]);
        g_ex[(size_t)slot * 4 + h] = ex;
        atomicAdd(&den[h], ex);
    }
    __syncthreads();

    /* pass 2: aggregate v, edge-attr moments, degree-norm branch */
    int   h0 = t >> 7, h1 = h0 + 2, hT = t >> 6;
    float agg0 = 0.f, agg1 = 0.f, Tc = 0.f, xwc = 0.f;
    float ddis = g_dis[d];
    for (int j = 0; j < deg; j++) {
        int slot = beg + j;
        int e    = g_eid[slot];
        int row  = g_ero[slot];
        float e0 = g_ex[(size_t)slot * 4 + h0];
        float e1 = g_ex[(size_t)slot * 4 + h1];
        float eT = g_ex[(size_t)slot * 4 + hT];
        const float* vr = g_v + (size_t)row * 512;
        agg0 += e0 * vr[t];
        agg1 += e1 * vr[256 + t];
        Tc   += eT * ea[(size_t)e * 64 + (t & 63)];
        if (t < 128)
            xwc += ddis * g_ewc[e] * g_dis[row] * g_xl[(size_t)row * 128 + t];
    }
    if (t < 128) sxw[t] = xwc;
    __syncthreads();

    float d0 = den[h0] + 1e-16f, d1 = den[h1] + 1e-16f, dT = den[hT] + 1e-16f;
    float s0 = den[h0] / d0,     s1 = den[h1] / d1;
    float xw = sxw[t & 127];
    g_o[(size_t)d * 512 + t]       += agg0 / d0 + s0 * ebias[t]       + xw;
    g_o[(size_t)d * 512 + 256 + t] += agg1 / d1 + s1 * ebias[256 + t] + xw;
    g_T[(size_t)d * 256 + t]        = Tc / dT;
}

/* ------------------------------------------------------------------ */
/* BatchNorm                                                            */
/* ------------------------------------------------------------------ */
__global__ void bnzero()
{
    int c = threadIdx.x;
    g_bns[c] = 0.f; g_bnq[c] = 0.f;
}

__global__ void bnstat(int n)
{
    int c  = threadIdx.x;
    int r0 = blockIdx.x * 128;
    float s = 0.f, q = 0.f;
    for (int r = 0; r < 128; r++) {
        float v = g_h1[(size_t)(r0 + r) * 128 + c];
        s += v; q += v * v;
    }
    atomicAdd(&g_bns[c], s);
    atomicAdd(&g_bnq[c], q);
}

__global__ void bnfin(const float* __restrict__ g, const float* __restrict__ b, int n)
{
    int c = threadIdx.x;
    float mu  = g_bns[c] / (float)n;
    float var = g_bnq[c] / (float)n - mu * mu;
    float sc  = g[c] * rsqrtf(var + 1e-5f);
    g_bsc[c] = sc;
    g_bsh[c] = b[c] - mu * sc;
}

__global__ void bnapply(float* __restrict__ out, int n)
{
    int i = blockIdx.x * 256 + threadIdx.x;
    if (i < n * 128) {
        int c = i & 127;
        out[i] = g_h1[i] * g_bsc[c] + g_bsh[c];
    }
}

/* ------------------------------------------------------------------ */
/* Top-k pooling                                                        */
/* ------------------------------------------------------------------ */
__global__ void wnorm_k(const float* __restrict__ w)
{
    __shared__ float s[128];
    int t = threadIdx.x;
    s[t] = w[t] * w[t];
    __syncthreads();
    for (int o = 64; o; o >>= 1) {
        if (t < o) s[t] += s[t + o];
        __syncthreads();
    }
    if (t == 0) g_wn[0] = sqrtf(s[0]) + 1e-16f;
}

__global__ void score_k(const float* __restrict__ h, const float* __restrict__ w, int n)
{
    int warp = (blockIdx.x * blockDim.x + threadIdx.x) >> 5;
    int lane = threadIdx.x & 31;
    if (warp >= n) return;
    float a = 0.f;
    const float* hr = h + (size_t)warp * 128;
    for (int c = lane; c < 128; c += 32) a += hr[c] * w[c];
#pragma unroll
    for (int o = 16; o; o >>= 1) a += __shfl_xor_sync(~0u, a, o);
    if (lane == 0) g_sc[warp] = tanhf(a / g_wn[0]);
}

__global__ void nidinit(int n)
{
    int i = blockIdx.x * 256 + threadIdx.x;
    if (i < n) g_nid[i] = -1;
}

/* one block per graph; threads == n_per (pow2 <= 1024). Bitonic sort:
   descending by value, ascending index on ties (matches jax top_k). */
__global__ void topk_pool(int n_per, int kk)
{
    __shared__ float sv[1024];
    __shared__ int   si[1024];
    int b = blockIdx.x, t = threadIdx.x;
    sv[t] = g_sc[b * n_per + t];
    si[t] = t;
    __syncthreads();
    for (int k2 = 2; k2 <= n_per; k2 <<= 1) {
        for (int j = k2 >> 1; j > 0; j >>= 1) {
            int ixj = t ^ j;
            if (ixj > t) {
                bool up = ((t & k2) == 0);
                float va = sv[t], vb = sv[ixj];
                int   ia = si[t], ib = si[ixj];
                bool aFirst = (va > vb) || (va == vb && ia < ib);
                if (up ? !aFirst : aFirst) {
                    sv[t] = vb; sv[ixj] = va;
                    si[t] = ib; si[ixj] = ia;
                }
            }
            __syncthreads();
        }
    }
    if (t < kk) {
        int gi = b * n_per + si[t];
        int r  = b * kk + t;
        g_vals[r] = sv[t];
        g_perm[r] = gi;
        g_nid[gi] = r;
    }
}

__global__ void gather_k(const float* __restrict__ hin, float* __restrict__ hout, int n_new)
{
    int i = blockIdx.x * 256 + threadIdx.x;
    if (i < n_new * 128) {
        int r = i >> 7, c = i & 127;
        hout[i] = hin[(size_t)g_perm[r] * 128 + c] * g_vals[r];
    }
}

__global__ void remap_k()
{
    int e = blockIdx.x * 256 + threadIdx.x;
    if (e < ETOT && g_keep[e]) {
        int nr = g_nid[g_row[e]], nc = g_nid[g_col[e]];
        if (nr >= 0 && nc >= 0) { g_row[e] = nr; g_col[e] = nc; }
        else { g_keep[e] = 0; g_row[e] = 0; g_col[e] = 0; g_ewc[e] = 0.f; }
    }
}

__global__ void reps_k(const float* __restrict__ h, int n_per, int which)
{
    int b = blockIdx.x, c = threadIdx.x;
    float mx = -3.4e38f, sm = 0.f;
    for (int r = 0; r < n_per; r++) {
        float v = h[(size_t)(b * n_per + r) * 128 + c];
        mx = fmaxf(mx, v);
        sm += v;
    }
    float* rep = which ? g_rep1 : g_rep0;
    rep[b * 256 + c]       = mx;
    rep[b * 256 + 128 + c] = sm / (float)n_per;
}

__global__ void add_rep(float* __restrict__ out)
{
    int i = blockIdx.x * 256 + threadIdx.x;
    if (i < BGR * 256) out[i] = g_rep0[i] + g_rep1[i];
}

/* ------------------------------------------------------------------ */
/* Host orchestration                                                   */
/* ------------------------------------------------------------------ */
extern "C" void kernel_launch(void* const* d_in, const int* in_sizes, int n_in,
                              void* d_out, int out_size)
{
    const float* x        = (const float*)d_in[0];
    const float* ea       = (const float*)d_in[1];
    const int*   ei       = (const int*)  d_in[2];
    const float* ew_in    = (const float*)d_in[3];
    const float* lin0_w   = (const float*)d_in[5];
    const float* lin0_b   = (const float*)d_in[6];
    const float* lin_w    = (const float*)d_in[7];
    const float* lin_b    = (const float*)d_in[8];
    const float* q_w      = (const float*)d_in[9];
    const float* q_b      = (const float*)d_in[10];
    const float* k_w      = (const float*)d_in[11];
    const float* k_b      = (const float*)d_in[12];
    const float* v_w      = (const float*)d_in[13];
    const float* v_b      = (const float*)d_in[14];
    const float* e_w      = (const float*)d_in[15];
    const float* e_b      = (const float*)d_in[16];
    const float* s_w      = (const float*)d_in[17];
    const float* s_b      = (const float*)d_in[18];
    const float* tr_w     = (const float*)d_in[19];
    const float* tr_b     = (const float*)d_in[20];
    const float* bn_g     = (const float*)d_in[21];
    const float* bn_b     = (const float*)d_in[22];
    const float* pool_w   = (const float*)d_in[23];
    float*       out      = (float*)d_out;

    float *p_xl, *p_q, *p_k, *p_v, *p_o, *p_P, *p_T, *p_h1, *p_hA, *p_hB;
    cudaGetSymbolAddress((void**)&p_xl, g_xl);
    cudaGetSymbolAddress((void**)&p_q,  g_q);
    cudaGetSymbolAddress((void**)&p_k,  g_k);
    cudaGetSymbolAddress((void**)&p_v,  g_v);
    cudaGetSymbolAddress((void**)&p_o,  g_o);
    cudaGetSymbolAddress((void**)&p_P,  g_P);
    cudaGetSymbolAddress((void**)&p_T,  g_T);
    cudaGetSymbolAddress((void**)&p_h1, g_h1);
    cudaGetSymbolAddress((void**)&p_hA, g_hA);
    cudaGetSymbolAddress((void**)&p_hB, g_hB);

    const int EB = (ETOT + 255) / 256;

    /* edge state init (must run every call: graph replays mutate it) */
    einit<<<EB, 256>>>(ei, ew_in);

    auto run_layer = [&](const float* hin, int inF, int n,
                         const float* lw, const float* lb, int L, float* hout)
    {
        const float* qw  = q_w  + (size_t)L * 128 * 512;
        const float* qb  = q_b  + (size_t)L * 512;
        const float* kw  = k_w  + (size_t)L * 128 * 512;
        const float* kb  = k_b  + (size_t)L * 512;
        const float* vw  = v_w  + (size_t)L * 128 * 512;
        const float* vb  = v_b  + (size_t)L * 512;
        const float* eww = e_w  + (size_t)L * 64 * 512;
        const float* ebb = e_b  + (size_t)L * 512;
        const float* sw  = s_w  + (size_t)L * 128 * 512;
        const float* sb  = s_b  + (size_t)L * 512;
        const float* trw = tr_w + (size_t)L * 512 * 128;
        const float* trb = tr_b + (size_t)L * 128;
        const float* bg  = bn_g + (size_t)L * 128;
        const float* bb  = bn_b + (size_t)L * 128;

        int mb = n / 128;

        /* xl = hin @ lw + lb */
        sgemm128<<<dim3(1, mb), 256>>>(hin, inF, 0, lw, 128, 0, lb,
                                       p_xl, 128, 0, inF, 0);
        /* q, k, v, skip */
        sgemm128<<<dim3(4, mb), 256>>>(p_xl, 128, 0, qw, 512, 0, qb, p_q, 512, 0, 128, 0);
        sgemm128<<<dim3(4, mb), 256>>>(p_xl, 128, 0, kw, 512, 0, kb, p_k, 512, 0, 128, 0);
        sgemm128<<<dim3(4, mb), 256>>>(p_xl, 128, 0, vw, 512, 0, vb, p_v, 512, 0, 128, 0);
        sgemm128<<<dim3(4, mb), 256>>>(p_xl, 128, 0, sw, 512, 0, sb, p_o, 512, 0, 128, 0);
        /* P[n,h,64] = q_h @ e_w_h^T — all 4 heads in grid.z */
        sgemm_nt<<<dim3(1, n / 64, 4), 256>>>(p_q, 512, 128, eww, 512, 128,
                                              p_P, 256, 64, 128);
        qeb_k<<<n, 128>>>(ebb);

        /* degree + CSR */
        zero3<<<(n + 255) / 256, 256>>>(n);
        degcnt<<<EB, 256>>>();
        disk<<<(n + 255) / 256, 256>>>(n);
        scan_excl<<<1, 1024>>>(n);
        fillk<<<EB, 256>>>();

        /* attention + aggregation */
        node_kernel<<<n, 256>>>(ea, ebb);

        /* out += T @ e_w (block-diag per head) — 4 heads in grid.z */
        sgemm128<<<dim3(1, mb, 4), 256>>>(p_T, 256, 64, eww, 512, 128, nullptr,
                                          p_o, 512, 128, 64, 2);

        /* h1 = relu(out @ tr_w + tr_b) ; bn */
        sgemm128<<<dim3(1, mb), 256>>>(p_o, 512, 0, trw, 128, 0, trb,
                                       p_h1, 128, 0, 512, 1);
        bnzero<<<1, 128>>>();
        bnstat<<<n / 128, 128>>>(n);
        bnfin<<<1, 128>>>(bg, bb, n);
        bnapply<<<(n * 128 + 255) / 256, 256>>>(hout, n);
    };

    auto do_pool = [&](const float* hin, float* hout, int n_old, int n_per,
                       const float* w, int which)
    {
        int kk    = n_per / 2;
        int n_new = BGR * kk;
        wnorm_k<<<1, 128>>>(w);
        score_k<<<n_old / 8, 256>>>(hin, w, n_old);
        nidinit<<<(n_old + 255) / 256, 256>>>(n_old);
        topk_pool<<<BGR, n_per>>>(n_per, kk);
        gather_k<<<(n_new * 128 + 255) / 256, 256>>>(hin, hout, n_new);
        remap_k<<<EB, 256>>>();
        reps_k<<<BGR, 128>>>(hout, kk, which);
    };

    /* layer 0 */
    run_layer(x, 256, 32768, lin0_w, lin0_b, 0, p_hA);
    /* layer 1 + pool 1 */
    run_layer(p_hA, 128, 32768, lin_w + 0 * 128 * 128, lin_b + 0 * 128, 1, p_hB);
    do_pool(p_hB, p_hA, 32768, 1024, pool_w, 0);
    /* layer 2 (no pool) */
    run_layer(p_hA, 128, 16384, lin_w + 1 * 128 * 128, lin_b + 1 * 128, 2, p_hB);
    /* layer 3 + pool 2 */
    run_layer(p_hB, 128, 16384, lin_w + 2 * 128 * 128, lin_b + 2 * 128, 3, p_hA);
    do_pool(p_hA, p_hB, 16384, 512, pool_w + 128, 1);

    add_rep<<<32, 256>>>(out);
}

// round 4
// speedup vs baseline: 1.4399x; 1.2195x over previous
#include <cuda_runtime.h>
#include <math.h>
#include <stdint.h>

#define NMAX 32768
#define ETOT 262144
#define BGR  32
#define INVC 0.08838834764831845f   /* 1/sqrt(128) */

#define QOFF 0
#define KOFF ((size_t)NMAX*512)
#define VOFF ((size_t)NMAX*512*2)
#define OOFF ((size_t)NMAX*512*3)

/* ------------------------------------------------------------------ */
/* Static scratch (no allocations allowed)                              */
/* ------------------------------------------------------------------ */
__device__ float g_xl  [NMAX*128];
__device__ float g_qkvo[(size_t)NMAX*512*4];
__device__ float g_P   [NMAX*256];
__device__ float g_qeb [NMAX*4];
__device__ float g_T   [NMAX*256];
__device__ float g_ex  [ETOT*4];
__device__ float g_hA  [NMAX*128];
__device__ float g_hB  [NMAX*128];
__device__ float g_h1  [NMAX*128];
__device__ float g_dis [NMAX];
__device__ int   g_deg [NMAX];
__device__ int   g_cnt [NMAX];
__device__ int   g_fil [NMAX];
__device__ int   g_off [NMAX+1];
__device__ int   g_eid [ETOT];
__device__ int   g_ero [ETOT];
__device__ int   g_row [ETOT];
__device__ int   g_col [ETOT];
__device__ float g_ewc [ETOT];
__device__ int   g_keep[ETOT];
__device__ float g_wcat[4*128*512];
__device__ float g_bcat[4*512];
__device__ float g_wp  [128*256];
__device__ float g_bp  [256];
__device__ float g_bns[128];
__device__ float g_bnq[128];
__device__ float g_bsc[128];
__device__ float g_bsh[128];
__device__ float g_wn[1];
__device__ float g_sc  [NMAX];
__device__ float g_vals[NMAX];
__device__ int   g_perm[NMAX];
__device__ int   g_nid [NMAX];
__device__ float g_rep0[BGR*256];
__device__ float g_rep1[BGR*256];

/* ------------------------------------------------------------------ */
/* packed fp32x2 helpers (sm_103a FFMA2 — only reachable via PTX)       */
/* ------------------------------------------------------------------ */
__device__ __forceinline__ unsigned long long pk2(float lo, float hi)
{
    unsigned long long r;
    asm("mov.b64 %0, {%1, %2};" : "=l"(r) : "f"(lo), "f"(hi));
    return r;
}
__device__ __forceinline__ void upk2(unsigned long long v, float& lo, float& hi)
{
    asm("mov.b64 {%0, %1}, %2;" : "=f"(lo), "=f"(hi) : "l"(v));
}
__device__ __forceinline__ unsigned long long ffma2(unsigned long long a,
                                                    unsigned long long b,
                                                    unsigned long long c)
{
    unsigned long long d;
    asm("fma.rn.f32x2 %0, %1, %2, %3;" : "=l"(d) : "l"(a), "l"(b), "l"(c));
    return d;
}

/* ------------------------------------------------------------------ */
/* fp32 GEMM, 128x128 tile, 8x8 microtile, FFMA2, double-buffered.      */
/* C = op( A(MxK,lda) @ B(KxN,ldb) + bias ), per-z pointer strides.     */
/* flags: 1 = relu, 2 = accumulate into existing C.                     */
/* M%128==0, N%128==0, K%8==0, all pointers 16B-aligned.                */
/* ------------------------------------------------------------------ */
__global__ void __launch_bounds__(256, 2)
sgemm128(const float* __restrict__ A, int lda, long az,
         const float* __restrict__ B, int ldb, long bz,
         const float* __restrict__ bias, long biasz,
         float* __restrict__ C, int ldc, long cz,
         int K, int flags)
{
    A += (long)blockIdx.z * az;
    B += (long)blockIdx.z * bz;
    C += (long)blockIdx.z * cz;
    if (bias) bias += (long)blockIdx.z * biasz;

    __shared__ float As[2][8][128];
    __shared__ float Bs[2][8][128];

    int bm = blockIdx.y << 7, bn = blockIdx.x << 7;
    int t  = threadIdx.x;
    int ty = t >> 4, tx = t & 15;
    int ra = ty << 2, cb = tx << 2;

    int arow = t >> 1;            /* 0..127 */
    int akc  = (t & 1) << 2;      /* 0 or 4 */
    int brow = t >> 5;            /* 0..7   */
    int bcol = (t & 31) << 2;     /* 0..124 */

    const float* Ap = A + (size_t)(bm + arow) * lda + akc;
    const float* Bp = B + (size_t)brow * ldb + bn + bcol;

    unsigned long long acc2[8][4];
#pragma unroll
    for (int i = 0; i < 8; i++)
#pragma unroll
        for (int j = 0; j < 4; j++) acc2[i][j] = 0ull;

    float4 av = *(const float4*)Ap;
    float4 bv = *(const float4*)Bp;
    As[0][akc + 0][arow] = av.x;
    As[0][akc + 1][arow] = av.y;
    As[0][akc + 2][arow] = av.z;
    As[0][akc + 3][arow] = av.w;
    *(float4*)&Bs[0][brow][bcol] = bv;
    __syncthreads();

    int buf = 0;
    for (int k0 = 0; k0 < K; k0 += 8) {
        bool more = (k0 + 8 < K);
        if (more) {
            av = *(const float4*)(Ap + k0 + 8);
            bv = *(const float4*)(Bp + (size_t)(k0 + 8) * ldb);
        }
#pragma unroll
        for (int kk = 0; kk < 8; kk++) {
            float4 a0 = *(float4*)&As[buf][kk][ra];
            float4 a1 = *(float4*)&As[buf][kk][64 + ra];
            float4 b0 = *(float4*)&Bs[buf][kk][cb];
            float4 b1 = *(float4*)&Bs[buf][kk][64 + cb];
            unsigned long long bp[4] = { pk2(b0.x, b0.y), pk2(b0.z, b0.w),
                                         pk2(b1.x, b1.y), pk2(b1.z, b1.w) };
            float a[8] = { a0.x, a0.y, a0.z, a0.w, a1.x, a1.y, a1.z, a1.w };
#pragma unroll
            for (int i = 0; i < 8; i++) {
                unsigned long long ap = pk2(a[i], a[i]);
#pragma unroll
                for (int j = 0; j < 4; j++)
                    acc2[i][j] = ffma2(ap, bp[j], acc2[i][j]);
            }
        }
        if (more) {
            As[buf ^ 1][akc + 0][arow] = av.x;
            As[buf ^ 1][akc + 1][arow] = av.y;
            As[buf ^ 1][akc + 2][arow] = av.z;
            As[buf ^ 1][akc + 3][arow] = av.w;
            *(float4*)&Bs[buf ^ 1][brow][bcol] = bv;
            __syncthreads();
            buf ^= 1;
        }
    }

    /* epilogue */
#pragma unroll
    for (int i = 0; i < 8; i++) {
        int r = bm + ((i < 4) ? (ra + i) : (64 + ra + i - 4));
#pragma unroll
        for (int g = 0; g < 2; g++) {
            int c = bn + (g ? 64 + cb : cb);
            float v0, v1, v2, v3;
            upk2(acc2[i][g * 2 + 0], v0, v1);
            upk2(acc2[i][g * 2 + 1], v2, v3);
            if (bias) {
                float4 bb = *(const float4*)&bias[c];
                v0 += bb.x; v1 += bb.y; v2 += bb.z; v3 += bb.w;
            }
            float* cp = &C[(size_t)r * ldc + c];
            if (flags & 2) {
                float4 old = *(float4*)cp;
                v0 += old.x; v1 += old.y; v2 += old.z; v3 += old.w;
            }
            if (flags & 1) {
                v0 = fmaxf(v0, 0.f); v1 = fmaxf(v1, 0.f);
                v2 = fmaxf(v2, 0.f); v3 = fmaxf(v3, 0.f);
            }
            float4 res = { v0, v1, v2, v3 };
            *(float4*)cp = res;
        }
    }
}

/* ------------------------------------------------------------------ */
/* Per-layer weight prep                                                */
/* ------------------------------------------------------------------ */
__global__ void catqkvs(const float* __restrict__ qw, const float* __restrict__ kw,
                        const float* __restrict__ vw, const float* __restrict__ sw,
                        const float* __restrict__ qb, const float* __restrict__ kb,
                        const float* __restrict__ vb, const float* __restrict__ sb)
{
    int i = blockIdx.x * 256 + threadIdx.x;
    if (i < 4 * 65536) {
        int z = i >> 16, r = i & 65535;
        const float* s = (z == 0) ? qw : (z == 1) ? kw : (z == 2) ? vw : sw;
        g_wcat[i] = s[r];
    }
    if (i < 4 * 512) {
        int z = i >> 9, r = i & 511;
        const float* s = (z == 0) ? qb : (z == 1) ? kb : (z == 2) ? vb : sb;
        g_bcat[i] = s[r];
    }
}

/* W_P[c2, h*64+f] = sum_c qw[c2,h*128+c] * e_w[f,h*128+c]   (warp/out) */
__global__ void wp_build(const float* __restrict__ qw, const float* __restrict__ eww)
{
    int gw   = (blockIdx.x * 256 + threadIdx.x) >> 5;   /* 0..32767 */
    int lane = threadIdx.x & 31;
    int c2 = gw >> 8, j = gw & 255;
    int h = j >> 6, f = j & 63;
    const float* a = qw  + c2 * 512 + h * 128;
    const float* b = eww + f  * 512 + h * 128;
    float s = 0.f;
#pragma unroll
    for (int c = lane; c < 128; c += 32) s += a[c] * b[c];
#pragma unroll
    for (int o = 16; o; o >>= 1) s += __shfl_xor_sync(~0u, s, o);
    if (lane == 0) g_wp[c2 * 256 + j] = s;
}

/* b_P[h*64+f] = sum_c qb[h*128+c] * e_w[f,h*128+c] */
__global__ void bp_build(const float* __restrict__ qb, const float* __restrict__ eww)
{
    int gw   = (blockIdx.x * 256 + threadIdx.x) >> 5;   /* 0..255 */
    int lane = threadIdx.x & 31;
    int h = gw >> 6, f = gw & 63;
    const float* a = qb  + h * 128;
    const float* b = eww + f * 512 + h * 128;
    float s = 0.f;
#pragma unroll
    for (int c = lane; c < 128; c += 32) s += a[c] * b[c];
#pragma unroll
    for (int o = 16; o; o >>= 1) s += __shfl_xor_sync(~0u, s, o);
    if (lane == 0) g_bp[gw] = s;
}

/* ------------------------------------------------------------------ */
/* Graph plumbing kernels                                               */
/* ------------------------------------------------------------------ */
__global__ void einit(const int* __restrict__ ei, const float* __restrict__ ew)
{
    int e = blockIdx.x * 256 + threadIdx.x;
    if (e < ETOT) {
        g_row[e] = ei[e];
        g_col[e] = ei[ETOT + e];
        g_ewc[e] = ew[e];
        g_keep[e] = 1;
    }
}

__global__ void zero3(int n)
{
    int i = blockIdx.x * 256 + threadIdx.x;
    if (i < n) { g_deg[i] = 0; g_cnt[i] = 0; g_fil[i] = 0; }
}

__global__ void degcnt()
{
    int e = blockIdx.x * 256 + threadIdx.x;
    if (e < ETOT && g_keep[e]) {
        atomicAdd(&g_deg[g_row[e]], 1);
        atomicAdd(&g_cnt[g_col[e]], 1);
    }
}

__global__ void disk(int n)
{
    int i = blockIdx.x * 256 + threadIdx.x;
    if (i < n) {
        int d = g_deg[i];
        g_dis[i] = d > 0 ? 1.0f / sqrtf((float)d) : 0.0f;
    }
}

__global__ void scan_excl(int n)
{
    __shared__ int part[1024];
    int t = threadIdx.x;
    int chunk = (n + 1023) >> 10;
    int s0 = t * chunk;
    int sum = 0;
    for (int i = 0; i < chunk; i++) {
        int idx = s0 + i;
        if (idx < n) sum += g_cnt[idx];
    }
    part[t] = sum;
    __syncthreads();
    for (int d = 1; d < 1024; d <<= 1) {
        int v = (t >= d) ? part[t - d] : 0;
        __syncthreads();
        part[t] += v;
        __syncthreads();
    }
    int run = (t == 0) ? 0 : part[t - 1];
    for (int i = 0; i < chunk; i++) {
        int idx = s0 + i;
        if (idx < n) { g_off[idx] = run; run += g_cnt[idx]; }
    }
    if (t == 1023) g_off[n] = part[1023];
}

__global__ void fillk()
{
    int e = blockIdx.x * 256 + threadIdx.x;
    if (e < ETOT && g_keep[e]) {
        int c = g_col[e];
        int p = g_off[c] + atomicAdd(&g_fil[c], 1);
        g_eid[p] = e;
        g_ero[p] = g_row[e];
    }
}

/* q . e_b per (node, head) */
__global__ void qeb_k(const float* __restrict__ ebias)
{
    int d = blockIdx.x;
    int h = threadIdx.x >> 5, lane = threadIdx.x & 31;
    float a = 0.f;
    const float* qr = g_qkvo + QOFF + (size_t)d * 512 + h * 128;
    const float* er = ebias + h * 128;
    for (int c = lane; c < 128; c += 32) a += qr[c] * er[c];
#pragma unroll
    for (int o = 16; o; o >>= 1) a += __shfl_xor_sync(~0u, a, o);
    if (lane == 0) g_qeb[d * 4 + h] = a;
}

/* ------------------------------------------------------------------ */
/* Main attention/aggregation kernel: one block (256 thr) per dst node */
/* ------------------------------------------------------------------ */
__global__ void node_kernel(const float* __restrict__ ea,
                            const float* __restrict__ ebias)
{
    int d   = blockIdx.x;
    int t   = threadIdx.x;
    int beg = g_off[d], deg = g_off[d + 1] - beg;
    if (deg == 0) { g_T[(size_t)d * 256 + t] = 0.f; return; }

    __shared__ float qs[512];
    __shared__ float Ps[256];
    __shared__ float sxw[128];
    __shared__ float wmax[8][4];
    __shared__ float hmax[4];
    __shared__ float den[4];

    qs[t]       = g_qkvo[QOFF + (size_t)d * 512 + t];
    qs[t + 256] = g_qkvo[QOFF + (size_t)d * 512 + 256 + t];
    Ps[t]       = g_P[(size_t)d * 256 + t];
    int w = t >> 5, lane = t & 31;
    if (lane == 0) { wmax[w][0] = wmax[w][1] = wmax[w][2] = wmax[w][3] = -3.4e38f; }
    if (t < 4) den[t] = 0.f;
    __syncthreads();

    float qe0 = g_qeb[d * 4 + 0], qe1 = g_qeb[d * 4 + 1],
          qe2 = g_qeb[d * 4 + 2], qe3 = g_qeb[d * 4 + 3];

    /* pass 1: alpha per edge (warp per edge) */
    float lm0 = -3.4e38f, lm1 = -3.4e38f, lm2 = -3.4e38f, lm3 = -3.4e38f;
    for (int j = w; j < deg; j += 8) {
        int slot = beg + j;
        int e    = g_eid[slot];
        int row  = g_ero[slot];
        const float* kr = g_qkvo + KOFF + (size_t)row * 512;
        float a0 = 0.f, a1 = 0.f, a2 = 0.f, a3 = 0.f;
        for (int c = lane; c < 128; c += 32) {
            a0 += qs[c]       * kr[c];
            a1 += qs[128 + c] * kr[128 + c];
            a2 += qs[256 + c] * kr[256 + c];
            a3 += qs[384 + c] * kr[384 + c];
        }
        const float* eae = ea + (size_t)e * 64;
        for (int f = lane; f < 64; f += 32) {
            float vv = eae[f];
            a0 += vv * Ps[f];
            a1 += vv * Ps[64 + f];
            a2 += vv * Ps[128 + f];
            a3 += vv * Ps[192 + f];
        }
#pragma unroll
        for (int o = 16; o; o >>= 1) {
            a0 += __shfl_xor_sync(~0u, a0, o);
            a1 += __shfl_xor_sync(~0u, a1, o);
            a2 += __shfl_xor_sync(~0u, a2, o);
            a3 += __shfl_xor_sync(~0u, a3, o);
        }
        if (lane == 0) {
            float al0 = (a0 + qe0) * INVC;
            float al1 = (a1 + qe1) * INVC;
            float al2 = (a2 + qe2) * INVC;
            float al3 = (a3 + qe3) * INVC;
            g_ex[(size_t)slot * 4 + 0] = al0;
            g_ex[(size_t)slot * 4 + 1] = al1;
            g_ex[(size_t)slot * 4 + 2] = al2;
            g_ex[(size_t)slot * 4 + 3] = al3;
            lm0 = fmaxf(lm0, al0); lm1 = fmaxf(lm1, al1);
            lm2 = fmaxf(lm2, al2); lm3 = fmaxf(lm3, al3);
        }
    }
    if (lane == 0) { wmax[w][0] = lm0; wmax[w][1] = lm1; wmax[w][2] = lm2; wmax[w][3] = lm3; }
    __syncthreads();
    if (t < 4) {
        float m = -3.4e38f;
        for (int ww = 0; ww < 8; ww++) m = fmaxf(m, wmax[ww][t]);
        hmax[t] = m;
    }
    __syncthreads();

    /* pass 1.5: exp + den */
    for (int t2 = t; t2 < deg * 4; t2 += 256) {
        int slot = beg + (t2 >> 2);
        int h    = t2 & 3;
        float ex = __expf(g_ex[(size_t)slot * 4 + h] - hmax[h]);
        g_ex[(size_t)slot * 4 + h] = ex;
        atomicAdd(&den[h], ex);
    }
    __syncthreads();

    /* pass 2: aggregate v, edge-attr moments, degree-norm branch */
    int   h0 = t >> 7, h1 = h0 + 2, hT = t >> 6;
    float agg0 = 0.f, agg1 = 0.f, Tc = 0.f, xwc = 0.f;
    float ddis = g_dis[d];
    for (int j = 0; j < deg; j++) {
        int slot = beg + j;
        int e    = g_eid[slot];
        int row  = g_ero[slot];
        float e0 = g_ex[(size_t)slot * 4 + h0];
        float e1 = g_ex[(size_t)slot * 4 + h1];
        float eT = g_ex[(size_t)slot * 4 + hT];
        const float* vr = g_qkvo + VOFF + (size_t)row * 512;
        agg0 += e0 * vr[t];
        agg1 += e1 * vr[256 + t];
        Tc   += eT * ea[(size_t)e * 64 + (t & 63)];
        if (t < 128)
            xwc += ddis * g_ewc[e] * g_dis[row] * g_xl[(size_t)row * 128 + t];
    }
    if (t < 128) sxw[t] = xwc;
    __syncthreads();

    float d0 = den[h0] + 1e-16f, d1 = den[h1] + 1e-16f, dT = den[hT] + 1e-16f;
    float s0 = den[h0] / d0,     s1 = den[h1] / d1;
    float xw = sxw[t & 127];
    g_qkvo[OOFF + (size_t)d * 512 + t]       += agg0 / d0 + s0 * ebias[t]       + xw;
    g_qkvo[OOFF + (size_t)d * 512 + 256 + t] += agg1 / d1 + s1 * ebias[256 + t] + xw;
    g_T[(size_t)d * 256 + t]                  = Tc / dT;
}

/* ------------------------------------------------------------------ */
/* BatchNorm                                                            */
/* ------------------------------------------------------------------ */
__global__ void bnzero()
{
    int c = threadIdx.x;
    g_bns[c] = 0.f; g_bnq[c] = 0.f;
}

__global__ void bnstat(int n)
{
    int c  = threadIdx.x;
    int r0 = blockIdx.x * 128;
    float s = 0.f, q = 0.f;
    for (int r = 0; r < 128; r++) {
        float v = g_h1[(size_t)(r0 + r) * 128 + c];
        s += v; q += v * v;
    }
    atomicAdd(&g_bns[c], s);
    atomicAdd(&g_bnq[c], q);
}

__global__ void bnfin(const float* __restrict__ g, const float* __restrict__ b, int n)
{
    int c = threadIdx.x;
    float mu  = g_bns[c] / (float)n;
    float var = g_bnq[c] / (float)n - mu * mu;
    float sc  = g[c] * rsqrtf(var + 1e-5f);
    g_bsc[c] = sc;
    g_bsh[c] = b[c] - mu * sc;
}

__global__ void bnapply(float* __restrict__ out, int n)
{
    int i = blockIdx.x * 256 + threadIdx.x;
    if (i < n * 128) {
        int c = i & 127;
        out[i] = g_h1[i] * g_bsc[c] + g_bsh[c];
    }
}

/* ------------------------------------------------------------------ */
/* Top-k pooling                                                        */
/* ------------------------------------------------------------------ */
__global__ void wnorm_k(const float* __restrict__ w)
{
    __shared__ float s[128];
    int t = threadIdx.x;
    s[t] = w[t] * w[t];
    __syncthreads();
    for (int o = 64; o; o >>= 1) {
        if (t < o) s[t] += s[t + o];
        __syncthreads();
    }
    if (t == 0) g_wn[0] = sqrtf(s[0]) + 1e-16f;
}

__global__ void score_k(const float* __restrict__ h, const float* __restrict__ w, int n)
{
    int warp = (blockIdx.x * blockDim.x + threadIdx.x) >> 5;
    int lane = threadIdx.x & 31;
    if (warp >= n) return;
    float a = 0.f;
    const float* hr = h + (size_t)warp * 128;
    for (int c = lane; c < 128; c += 32) a += hr[c] * w[c];
#pragma unroll
    for (int o = 16; o; o >>= 1) a += __shfl_xor_sync(~0u, a, o);
    if (lane == 0) g_sc[warp] = tanhf(a / g_wn[0]);
}

__global__ void nidinit(int n)
{
    int i = blockIdx.x * 256 + threadIdx.x;
    if (i < n) g_nid[i] = -1;
}

/* one block per graph; threads == n_per (pow2 <= 1024). Bitonic sort:
   descending by value, ascending index on ties (matches jax top_k). */
__global__ void topk_pool(int n_per, int kk)
{
    __shared__ float sv[1024];
    __shared__ int   si[1024];
    int b = blockIdx.x, t = threadIdx.x;
    sv[t] = g_sc[b * n_per + t];
    si[t] = t;
    __syncthreads();
    for (int k2 = 2; k2 <= n_per; k2 <<= 1) {
        for (int j = k2 >> 1; j > 0; j >>= 1) {
            int ixj = t ^ j;
            if (ixj > t) {
                bool up = ((t & k2) == 0);
                float va = sv[t], vb = sv[ixj];
                int   ia = si[t], ib = si[ixj];
                bool aFirst = (va > vb) || (va == vb && ia < ib);
                if (up ? !aFirst : aFirst) {
                    sv[t] = vb; sv[ixj] = va;
                    si[t] = ib; si[ixj] = ia;
                }
            }
            __syncthreads();
        }
    }
    if (t < kk) {
        int gi = b * n_per + si[t];
        int r  = b * kk + t;
        g_vals[r] = sv[t];
        g_perm[r] = gi;
        g_nid[gi] = r;
    }
}

__global__ void gather_k(const float* __restrict__ hin, float* __restrict__ hout, int n_new)
{
    int i = blockIdx.x * 256 + threadIdx.x;
    if (i < n_new * 128) {
        int r = i >> 7, c = i & 127;
        hout[i] = hin[(size_t)g_perm[r] * 128 + c] * g_vals[r];
    }
}

__global__ void remap_k()
{
    int e = blockIdx.x * 256 + threadIdx.x;
    if (e < ETOT && g_keep[e]) {
        int nr = g_nid[g_row[e]], nc = g_nid[g_col[e]];
        if (nr >= 0 && nc >= 0) { g_row[e] = nr; g_col[e] = nc; }
        else { g_keep[e] = 0; g_row[e] = 0; g_col[e] = 0; g_ewc[e] = 0.f; }
    }
}

__global__ void reps_k(const float* __restrict__ h, int n_per, int which)
{
    int b = blockIdx.x, c = threadIdx.x;
    float mx = -3.4e38f, sm = 0.f;
    for (int r = 0; r < n_per; r++) {
        float v = h[(size_t)(b * n_per + r) * 128 + c];
        mx = fmaxf(mx, v);
        sm += v;
    }
    float* rep = which ? g_rep1 : g_rep0;
    rep[b * 256 + c]       = mx;
    rep[b * 256 + 128 + c] = sm / (float)n_per;
}

__global__ void add_rep(float* __restrict__ out)
{
    int i = blockIdx.x * 256 + threadIdx.x;
    if (i < BGR * 256) out[i] = g_rep0[i] + g_rep1[i];
}

/* ------------------------------------------------------------------ */
/* Host orchestration                                                   */
/* ------------------------------------------------------------------ */
extern "C" void kernel_launch(void* const* d_in, const int* in_sizes, int n_in,
                              void* d_out, int out_size)
{
    const float* x        = (const float*)d_in[0];
    const float* ea       = (const float*)d_in[1];
    const int*   ei       = (const int*)  d_in[2];
    const float* ew_in    = (const float*)d_in[3];
    const float* lin0_w   = (const float*)d_in[5];
    const float* lin0_b   = (const float*)d_in[6];
    const float* lin_w    = (const float*)d_in[7];
    const float* lin_b    = (const float*)d_in[8];
    const float* q_w      = (const float*)d_in[9];
    const float* q_b      = (const float*)d_in[10];
    const float* k_w      = (const float*)d_in[11];
    const float* k_b      = (const float*)d_in[12];
    const float* v_w      = (const float*)d_in[13];
    const float* v_b      = (const float*)d_in[14];
    const float* e_w      = (const float*)d_in[15];
    const float* e_b      = (const float*)d_in[16];
    const float* s_w      = (const float*)d_in[17];
    const float* s_b      = (const float*)d_in[18];
    const float* tr_w     = (const float*)d_in[19];
    const float* tr_b     = (const float*)d_in[20];
    const float* bn_g     = (const float*)d_in[21];
    const float* bn_b     = (const float*)d_in[22];
    const float* pool_w   = (const float*)d_in[23];
    float*       out      = (float*)d_out;

    float *p_xl, *p_qkvo, *p_P, *p_T, *p_h1, *p_hA, *p_hB, *p_wcat, *p_bcat, *p_wp, *p_bp;
    cudaGetSymbolAddress((void**)&p_xl,   g_xl);
    cudaGetSymbolAddress((void**)&p_qkvo, g_qkvo);
    cudaGetSymbolAddress((void**)&p_P,    g_P);
    cudaGetSymbolAddress((void**)&p_T,    g_T);
    cudaGetSymbolAddress((void**)&p_h1,   g_h1);
    cudaGetSymbolAddress((void**)&p_hA,   g_hA);
    cudaGetSymbolAddress((void**)&p_hB,   g_hB);
    cudaGetSymbolAddress((void**)&p_wcat, g_wcat);
    cudaGetSymbolAddress((void**)&p_bcat, g_bcat);
    cudaGetSymbolAddress((void**)&p_wp,   g_wp);
    cudaGetSymbolAddress((void**)&p_bp,   g_bp);

    float* p_o = p_qkvo + OOFF;

    const int EB = (ETOT + 255) / 256;

    /* edge state init (must run every call: graph replays mutate it) */
    einit<<<EB, 256>>>(ei, ew_in);

    auto run_layer = [&](const float* hin, int inF, int n,
                         const float* lw, const float* lb, int L, float* hout)
    {
        const float* qw  = q_w  + (size_t)L * 128 * 512;
        const float* qb  = q_b  + (size_t)L * 512;
        const float* kw  = k_w  + (size_t)L * 128 * 512;
        const float* kb  = k_b  + (size_t)L * 512;
        const float* vw  = v_w  + (size_t)L * 128 * 512;
        const float* vb  = v_b  + (size_t)L * 512;
        const float* eww = e_w  + (size_t)L * 64 * 512;
        const float* ebb = e_b  + (size_t)L * 512;
        const float* sw  = s_w  + (size_t)L * 128 * 512;
        const float* sb  = s_b  + (size_t)L * 512;
        const float* trw = tr_w + (size_t)L * 512 * 128;
        const float* trb = tr_b + (size_t)L * 128;
        const float* bg  = bn_g + (size_t)L * 128;
        const float* bb  = bn_b + (size_t)L * 128;

        int mb = n / 128;

        /* weight prep */
        catqkvs<<<1024, 256>>>(qw, kw, vw, sw, qb, kb, vb, sb);
        wp_build<<<4096, 256>>>(qw, eww);
        bp_build<<<32, 256>>>(qb, eww);

        /* xl = hin @ lw + lb */
        sgemm128<<<dim3(1, mb), 256>>>(hin, inF, 0, lw, 128, 0, lb, 0,
                                       p_xl, 128, 0, inF, 0);
        /* fused q|k|v|skip : z = 4 */
        sgemm128<<<dim3(4, mb, 4), 256>>>(p_xl, 128, 0, p_wcat, 512, 65536,
                                          p_bcat, 512,
                                          p_qkvo, 512, (long)NMAX * 512, 128, 0);
        /* P = xl @ W_P + b_P */
        sgemm128<<<dim3(2, mb), 256>>>(p_xl, 128, 0, p_wp, 256, 0, p_bp, 0,
                                       p_P, 256, 0, 128, 0);
        qeb_k<<<n, 128>>>(ebb);

        /* degree + CSR */
        zero3<<<(n + 255) / 256, 256>>>(n);
        degcnt<<<EB, 256>>>();
        disk<<<(n + 255) / 256, 256>>>(n);
        scan_excl<<<1, 1024>>>(n);
        fillk<<<EB, 256>>>();

        /* attention + aggregation */
        node_kernel<<<n, 256>>>(ea, ebb);

        /* out += T @ e_w (block-diag per head) — 4 heads in grid.z */
        sgemm128<<<dim3(1, mb, 4), 256>>>(p_T, 256, 64, eww, 512, 128, nullptr, 0,
                                          p_o, 512, 128, 64, 2);

        /* h1 = relu(out @ tr_w + tr_b) ; bn */
        sgemm128<<<dim3(1, mb), 256>>>(p_o, 512, 0, trw, 128, 0, trb, 0,
                                       p_h1, 128, 0, 512, 1);
        bnzero<<<1, 128>>>();
        bnstat<<<n / 128, 128>>>(n);
        bnfin<<<1, 128>>>(bg, bb, n);
        bnapply<<<(n * 128 + 255) / 256, 256>>>(hout, n);
    };

    auto do_pool = [&](const float* hin, float* hout, int n_old, int n_per,
                       const float* w, int which)
    {
        int kk    = n_per / 2;
        int n_new = BGR * kk;
        wnorm_k<<<1, 128>>>(w);
        score_k<<<n_old / 8, 256>>>(hin, w, n_old);
        nidinit<<<(n_old + 255) / 256, 256>>>(n_old);
        topk_pool<<<BGR, n_per>>>(n_per, kk);
        gather_k<<<(n_new * 128 + 255) / 256, 256>>>(hin, hout, n_new);
        remap_k<<<EB, 256>>>();
        reps_k<<<BGR, 128>>>(hout, kk, which);
    };

    /* layer 0 */
    run_layer(x, 256, 32768, lin0_w, lin0_b, 0, p_hA);
    /* layer 1 + pool 1 */
    run_layer(p_hA, 128, 32768, lin_w + 0 * 128 * 128, lin_b + 0 * 128, 1, p_hB);
    do_pool(p_hB, p_hA, 32768, 1024, pool_w, 0);
    /* layer 2 (no pool) */
    run_layer(p_hA, 128, 16384, lin_w + 1 * 128 * 128, lin_b + 1 * 128, 2, p_hB);
    /* layer 3 + pool 2 */
    run_layer(p_hB, 128, 16384, lin_w + 2 * 128 * 128, lin_b + 2 * 128, 3, p_hA);
    do_pool(p_hA, p_hB, 16384, 512, pool_w + 128, 1);

    add_rep<<<32, 256>>>(out);
}

// round 5
// speedup vs baseline: 1.5920x; 1.1057x over previous
#include <cuda_runtime.h>
#include <cuda_bf16.h>
#include <math.h>
#include <stdint.h>

#define NMAX 32768
#define ETOT 262144
#define BGR  32
#define INVC 0.08838834764831845f   /* 1/sqrt(128) */

#define QOFF 0
#define KOFF ((size_t)NMAX*512)
#define VOFF ((size_t)NMAX*512*2)
#define OOFF ((size_t)NMAX*512*3)

/* ------------------------------------------------------------------ */
/* Static scratch (no allocations allowed)                              */
/* ------------------------------------------------------------------ */
__device__ float g_xl  [NMAX*128];
__device__ float g_qkvo[(size_t)NMAX*512*4];
__device__ float g_P   [NMAX*256];
__device__ float g_T   [NMAX*256];
__device__ float g_ex  [ETOT*4];
__device__ float g_hA  [NMAX*128];
__device__ float g_hB  [NMAX*128];
__device__ float g_h1  [NMAX*128];
__device__ float g_dis [NMAX];
__device__ int   g_deg [NMAX];
__device__ int   g_cnt [NMAX];
__device__ int   g_fil [NMAX];
__device__ int   g_off [NMAX+1];
__device__ int   g_eid [ETOT];
__device__ int   g_ero [ETOT];
__device__ int   g_row [ETOT];
__device__ int   g_col [ETOT];
__device__ float g_ewc [ETOT];
__device__ int   g_keep[ETOT];
__device__ float g_wcat[4*128*512];
__device__ float g_bcat[4*512];
__device__ float g_wp  [128*256];
__device__ float g_bp  [256];
__device__ float g_bns[128];
__device__ float g_bnq[128];
__device__ float g_bsc[128];
__device__ float g_bsh[128];
__device__ float g_wn[1];
__device__ float g_sc  [NMAX];
__device__ float g_vals[NMAX];
__device__ int   g_perm[NMAX];
__device__ int   g_nid [NMAX];
__device__ float g_rep0[BGR*256];
__device__ float g_rep1[BGR*256];

/* ------------------------------------------------------------------ */
/* Tensor-core GEMM (bf16x3 emulation of fp32)                          */
/* C = op( A(MxK,lda) @ B(KxN,ldb) + bias ), per-z pointer strides.     */
/* flags: 1 = relu, 2 = accumulate.  M%128==0, N%128==0, K%16==0.       */
/* ------------------------------------------------------------------ */
__device__ __forceinline__ uint32_t s2u(const void* p)
{
    return (uint32_t)__cvta_generic_to_shared(p);
}
__device__ __forceinline__ void ldsm4(uint32_t* r, uint32_t addr)
{
    asm volatile("ldmatrix.sync.aligned.m8n8.x4.shared.b16 {%0,%1,%2,%3}, [%4];"
                 : "=r"(r[0]), "=r"(r[1]), "=r"(r[2]), "=r"(r[3]) : "r"(addr));
}
__device__ __forceinline__ void ldsm4t(uint32_t* r, uint32_t addr)
{
    asm volatile("ldmatrix.sync.aligned.m8n8.x4.trans.shared.b16 {%0,%1,%2,%3}, [%4];"
                 : "=r"(r[0]), "=r"(r[1]), "=r"(r[2]), "=r"(r[3]) : "r"(addr));
}
__device__ __forceinline__ void hmma(float* d, const uint32_t* a, const uint32_t* b)
{
    asm volatile(
        "mma.sync.aligned.m16n8k16.row.col.f32.bf16.bf16.f32 "
        "{%0,%1,%2,%3}, {%4,%5,%6,%7}, {%8,%9}, {%0,%1,%2,%3};"
        : "+f"(d[0]), "+f"(d[1]), "+f"(d[2]), "+f"(d[3])
        : "r"(a[0]), "r"(a[1]), "r"(a[2]), "r"(a[3]), "r"(b[0]), "r"(b[1]));
}
__device__ __forceinline__ unsigned short f2b(float x)
{
    __nv_bfloat16 b = __float2bfloat16(x);
    return *(unsigned short*)&b;
}
__device__ __forceinline__ float b2f(unsigned short u)
{
    __nv_bfloat16 b = *(__nv_bfloat16*)&u;
    return __bfloat162float(b);
}
/* split float4 into hi/lo bf16 quads and store (8B each) */
__device__ __forceinline__ void cvst4(__nv_bfloat16* ph, __nv_bfloat16* pl, float4 v)
{
    float xs[4] = { v.x, v.y, v.z, v.w };
    unsigned short h[4], l[4];
#pragma unroll
    for (int i = 0; i < 4; i++) {
        h[i] = f2b(xs[i]);
        l[i] = f2b(xs[i] - b2f(h[i]));
    }
    uint2 hp = { (uint32_t)h[0] | ((uint32_t)h[1] << 16),
                 (uint32_t)h[2] | ((uint32_t)h[3] << 16) };
    uint2 lp = { (uint32_t)l[0] | ((uint32_t)l[1] << 16),
                 (uint32_t)l[2] | ((uint32_t)l[3] << 16) };
    *(uint2*)ph = hp;
    *(uint2*)pl = lp;
}

#define A_LD 24        /* bf16 elems per A smem row (16 + 8 pad) */
#define B_LD 136       /* bf16 elems per B smem row (128 + 8 pad) */
#define A_TILE (128*A_LD)
#define B_TILE (16*B_LD)

__global__ void __launch_bounds__(256)
tgemm(const float* __restrict__ A, int lda, long az,
      const float* __restrict__ B, int ldb, long bz,
      const float* __restrict__ bias, long biasz,
      float* __restrict__ C, int ldc, long cz,
      int K, int flags)
{
    A += (long)blockIdx.z * az;
    B += (long)blockIdx.z * bz;
    C += (long)blockIdx.z * cz;
    if (bias) bias += (long)blockIdx.z * biasz;

    /* [buf][hi/lo][tile] */
    __shared__ __nv_bfloat16 sA[2][2][A_TILE];
    __shared__ __nv_bfloat16 sB[2][2][B_TILE];

    int bm = blockIdx.y << 7, bn = blockIdx.x << 7;
    int t  = threadIdx.x;
    int w  = t >> 5, lane = t & 31;
    int mw = w >> 1, nw = w & 1;
    int m0 = mw << 5, n0 = nw << 6;

    /* global-load mapping */
    int ar = t >> 2, ac = (t & 3) << 2;     /* A rows ar, ar+64 */
    int br = t >> 5, bc = (t & 31) << 2;    /* B rows br, br+8  */

    const float* ApA = A + (size_t)(bm + ar) * lda + ac;
    const float* ApB = A + (size_t)(bm + ar + 64) * lda + ac;
    const float* BpA = B + (size_t)br * ldb + bn + bc;
    const float* BpB = B + (size_t)(br + 8) * ldb + bn + bc;

    /* smem store pointers (element offsets) */
    int aoff0 = ar * A_LD + ac;
    int aoff1 = (ar + 64) * A_LD + ac;
    int boff0 = br * B_LD + bc;
    int boff1 = (br + 8) * B_LD + bc;

    /* ldmatrix addresses (bytes) */
    uint32_t aAddr = s2u(&sA[0][0][(m0 + (lane & 15)) * A_LD + ((lane >> 4) << 3)]);
    uint32_t bAddr = s2u(&sB[0][0][(lane & 15) * B_LD + n0 + ((lane >> 4) << 3)]);
    const uint32_t A_HL  = A_TILE * 2;      /* hi→lo byte offset   */
    const uint32_t A_BUF = 2 * A_HL;        /* buf stride          */
    const uint32_t A_MT  = 16 * A_LD * 2;   /* m16 tile stride     */
    const uint32_t B_HL  = B_TILE * 2;
    const uint32_t B_BUF = 2 * B_HL;
    const uint32_t B_G   = 16 * 2;          /* n16 group stride    */

    float acc[2][8][4];
#pragma unroll
    for (int i = 0; i < 2; i++)
#pragma unroll
        for (int j = 0; j < 8; j++)
#pragma unroll
            for (int q = 0; q < 4; q++) acc[i][j][q] = 0.f;

    int nstage = K >> 4;

    /* prologue: stage 0 */
    {
        float4 a0 = *(const float4*)(ApA);
        float4 a1 = *(const float4*)(ApB);
        float4 b0 = *(const float4*)(BpA);
        float4 b1 = *(const float4*)(BpB);
        cvst4(&sA[0][0][aoff0], &sA[0][1][aoff0], a0);
        cvst4(&sA[0][0][aoff1], &sA[0][1][aoff1], a1);
        cvst4(&sB[0][0][boff0], &sB[0][1][boff0], b0);
        cvst4(&sB[0][0][boff1], &sB[0][1][boff1], b1);
    }
    __syncthreads();

    int buf = 0;
    for (int s = 0; s < nstage; s++) {
        int k1 = (s + 1) << 4;
        float4 na0, na1, nb0, nb1;
        bool more = (s + 1 < nstage);
        if (more) {
            na0 = *(const float4*)(ApA + k1);
            na1 = *(const float4*)(ApB + k1);
            nb0 = *(const float4*)(BpA + (size_t)k1 * ldb);
            nb1 = *(const float4*)(BpB + (size_t)k1 * ldb);
        }

        uint32_t ah[2][4], al[2][4];
#pragma unroll
        for (int mt = 0; mt < 2; mt++) {
            ldsm4(ah[mt], aAddr + buf * A_BUF + mt * A_MT);
            ldsm4(al[mt], aAddr + buf * A_BUF + mt * A_MT + A_HL);
        }
#pragma unroll
        for (int g = 0; g < 4; g++) {
            uint32_t bh[4], bl[4];
            ldsm4t(bh, bAddr + buf * B_BUF + g * B_G);
            ldsm4t(bl, bAddr + buf * B_BUF + g * B_G + B_HL);
#pragma unroll
            for (int mt = 0; mt < 2; mt++) {
                hmma(acc[mt][2*g],   ah[mt], bh);
                hmma(acc[mt][2*g],   ah[mt], bl);
                hmma(acc[mt][2*g],   al[mt], bh);
                hmma(acc[mt][2*g+1], ah[mt], bh + 2);
                hmma(acc[mt][2*g+1], ah[mt], bl + 2);
                hmma(acc[mt][2*g+1], al[mt], bh + 2);
            }
        }
        if (more) {
            int nb = buf ^ 1;
            cvst4(&sA[nb][0][aoff0], &sA[nb][1][aoff0], na0);
            cvst4(&sA[nb][0][aoff1], &sA[nb][1][aoff1], na1);
            cvst4(&sB[nb][0][boff0], &sB[nb][1][boff0], nb0);
            cvst4(&sB[nb][0][boff1], &sB[nb][1][boff1], nb1);
            __syncthreads();
            buf = nb;
        }
    }

    /* epilogue */
#pragma unroll
    for (int mt = 0; mt < 2; mt++) {
        int r0 = bm + m0 + mt * 16 + (lane >> 2);
#pragma unroll
        for (int nt = 0; nt < 8; nt++) {
            int c = bn + n0 + nt * 8 + ((lane & 3) << 1);
            float bb0 = 0.f, bb1 = 0.f;
            if (bias) { bb0 = bias[c]; bb1 = bias[c + 1]; }
#pragma unroll
            for (int rr = 0; rr < 2; rr++) {
                int r = r0 + rr * 8;
                float v0 = acc[mt][nt][rr * 2 + 0] + bb0;
                float v1 = acc[mt][nt][rr * 2 + 1] + bb1;
                float* cp = &C[(size_t)r * ldc + c];
                if (flags & 2) { v0 += cp[0]; v1 += cp[1]; }
                if (flags & 1) { v0 = fmaxf(v0, 0.f); v1 = fmaxf(v1, 0.f); }
                float2 res = { v0, v1 };
                *(float2*)cp = res;
            }
        }
    }
}

/* ------------------------------------------------------------------ */
/* Per-layer weight prep                                                */
/* ------------------------------------------------------------------ */
__global__ void catqkvs(const float* __restrict__ qw, const float* __restrict__ kw,
                        const float* __restrict__ vw, const float* __restrict__ sw,
                        const float* __restrict__ qb, const float* __restrict__ kb,
                        const float* __restrict__ vb, const float* __restrict__ sb)
{
    int i = blockIdx.x * 256 + threadIdx.x;
    if (i < 4 * 65536) {
        int z = i >> 16, r = i & 65535;
        const float* s = (z == 0) ? qw : (z == 1) ? kw : (z == 2) ? vw : sw;
        g_wcat[i] = s[r];
    }
    if (i < 4 * 512) {
        int z = i >> 9, r = i & 511;
        const float* s = (z == 0) ? qb : (z == 1) ? kb : (z == 2) ? vb : sb;
        g_bcat[i] = s[r];
    }
}

/* W_P[c2, h*64+f] = sum_c qw[c2,h*128+c] * e_w[f,h*128+c]
   plus b_P[h*64+f] = sum_c qb[h*128+c] * e_w[f,h*128+c]  (warp per out) */
__global__ void wpbp_build(const float* __restrict__ qw, const float* __restrict__ qb,
                           const float* __restrict__ eww)
{
    int gw   = (blockIdx.x * 256 + threadIdx.x) >> 5;
    int lane = threadIdx.x & 31;
    if (gw < 32768) {
        int c2 = gw >> 8, j = gw & 255;
        int h = j >> 6, f = j & 63;
        const float* a = qw  + c2 * 512 + h * 128;
        const float* b = eww + f  * 512 + h * 128;
        float s = 0.f;
#pragma unroll
        for (int c = lane; c < 128; c += 32) s += a[c] * b[c];
#pragma unroll
        for (int o = 16; o; o >>= 1) s += __shfl_xor_sync(~0u, s, o);
        if (lane == 0) g_wp[c2 * 256 + j] = s;
    } else if (gw < 33024) {
        int j = gw - 32768;
        int h = j >> 6, f = j & 63;
        const float* a = qb  + h * 128;
        const float* b = eww + f * 512 + h * 128;
        float s = 0.f;
#pragma unroll
        for (int c = lane; c < 128; c += 32) s += a[c] * b[c];
#pragma unroll
        for (int o = 16; o; o >>= 1) s += __shfl_xor_sync(~0u, s, o);
        if (lane == 0) g_bp[j] = s;
    }
}

/* ------------------------------------------------------------------ */
/* Graph plumbing kernels                                               */
/* ------------------------------------------------------------------ */
__global__ void einit(const int* __restrict__ ei, const float* __restrict__ ew)
{
    int e = blockIdx.x * 256 + threadIdx.x;
    if (e < ETOT) {
        g_row[e] = ei[e];
        g_col[e] = ei[ETOT + e];
        g_ewc[e] = ew[e];
        g_keep[e] = 1;
    }
}

__global__ void zero3(int n)
{
    int i = blockIdx.x * 256 + threadIdx.x;
    if (i < n) { g_deg[i] = 0; g_cnt[i] = 0; g_fil[i] = 0; }
}

__global__ void degcnt()
{
    int e = blockIdx.x * 256 + threadIdx.x;
    if (e < ETOT && g_keep[e]) {
        atomicAdd(&g_deg[g_row[e]], 1);
        atomicAdd(&g_cnt[g_col[e]], 1);
    }
}

__global__ void disk(int n)
{
    int i = blockIdx.x * 256 + threadIdx.x;
    if (i < n) {
        int d = g_deg[i];
        g_dis[i] = d > 0 ? 1.0f / sqrtf((float)d) : 0.0f;
    }
}

__global__ void scan_excl(int n)
{
    __shared__ int part[1024];
    int t = threadIdx.x;
    int chunk = (n + 1023) >> 10;
    int s0 = t * chunk;
    int sum = 0;
    for (int i = 0; i < chunk; i++) {
        int idx = s0 + i;
        if (idx < n) sum += g_cnt[idx];
    }
    part[t] = sum;
    __syncthreads();
    for (int d = 1; d < 1024; d <<= 1) {
        int v = (t >= d) ? part[t - d] : 0;
        __syncthreads();
        part[t] += v;
        __syncthreads();
    }
    int run = (t == 0) ? 0 : part[t - 1];
    for (int i = 0; i < chunk; i++) {
        int idx = s0 + i;
        if (idx < n) { g_off[idx] = run; run += g_cnt[idx]; }
    }
    if (t == 1023) g_off[n] = part[1023];
}

__global__ void fillk()
{
    int e = blockIdx.x * 256 + threadIdx.x;
    if (e < ETOT && g_keep[e]) {
        int c = g_col[e];
        int p = g_off[c] + atomicAdd(&g_fil[c], 1);
        g_eid[p] = e;
        g_ero[p] = g_row[e];
    }
}

/* ------------------------------------------------------------------ */
/* Main attention/aggregation kernel: one block (256 thr) per dst node */
/* ------------------------------------------------------------------ */
__global__ void node_kernel(const float* __restrict__ ea,
                            const float* __restrict__ ebias)
{
    int d   = blockIdx.x;
    int t   = threadIdx.x;
    int beg = g_off[d], deg = g_off[d + 1] - beg;
    if (deg == 0) { g_T[(size_t)d * 256 + t] = 0.f; return; }

    __shared__ float qs[512];
    __shared__ float Ps[256];
    __shared__ float sxw[128];
    __shared__ float wmax[8][4];
    __shared__ float hmax[4];
    __shared__ float den[4];
    __shared__ float sqe[4];

    qs[t]       = g_qkvo[QOFF + (size_t)d * 512 + t];
    qs[t + 256] = g_qkvo[QOFF + (size_t)d * 512 + 256 + t];
    Ps[t]       = g_P[(size_t)d * 256 + t];
    int w = t >> 5, lane = t & 31;
    if (lane == 0) { wmax[w][0] = wmax[w][1] = wmax[w][2] = wmax[w][3] = -3.4e38f; }
    if (t < 4) den[t] = 0.f;
    __syncthreads();

    /* q . e_b per head (warps 0-3) */
    if (w < 4) {
        float a = 0.f;
#pragma unroll
        for (int c = lane; c < 128; c += 32) a += qs[w * 128 + c] * ebias[w * 128 + c];
#pragma unroll
        for (int o = 16; o; o >>= 1) a += __shfl_xor_sync(~0u, a, o);
        if (lane == 0) sqe[w] = a;
    }
    __syncthreads();

    float qe0 = sqe[0], qe1 = sqe[1], qe2 = sqe[2], qe3 = sqe[3];

    /* pass 1: alpha per edge (warp per edge) */
    float lm0 = -3.4e38f, lm1 = -3.4e38f, lm2 = -3.4e38f, lm3 = -3.4e38f;
    for (int j = w; j < deg; j += 8) {
        int slot = beg + j;
        int e    = g_eid[slot];
        int row  = g_ero[slot];
        const float* kr = g_qkvo + KOFF + (size_t)row * 512;
        float a0 = 0.f, a1 = 0.f, a2 = 0.f, a3 = 0.f;
        for (int c = lane; c < 128; c += 32) {
            a0 += qs[c]       * kr[c];
            a1 += qs[128 + c] * kr[128 + c];
            a2 += qs[256 + c] * kr[256 + c];
            a3 += qs[384 + c] * kr[384 + c];
        }
        const float* eae = ea + (size_t)e * 64;
        for (int f = lane; f < 64; f += 32) {
            float vv = eae[f];
            a0 += vv * Ps[f];
            a1 += vv * Ps[64 + f];
            a2 += vv * Ps[128 + f];
            a3 += vv * Ps[192 + f];
        }
#pragma unroll
        for (int o = 16; o; o >>= 1) {
            a0 += __shfl_xor_sync(~0u, a0, o);
            a1 += __shfl_xor_sync(~0u, a1, o);
            a2 += __shfl_xor_sync(~0u, a2, o);
            a3 += __shfl_xor_sync(~0u, a3, o);
        }
        if (lane == 0) {
            float al0 = (a0 + qe0) * INVC;
            float al1 = (a1 + qe1) * INVC;
            float al2 = (a2 + qe2) * INVC;
            float al3 = (a3 + qe3) * INVC;
            g_ex[(size_t)slot * 4 + 0] = al0;
            g_ex[(size_t)slot * 4 + 1] = al1;
            g_ex[(size_t)slot * 4 + 2] = al2;
            g_ex[(size_t)slot * 4 + 3] = al3;
            lm0 = fmaxf(lm0, al0); lm1 = fmaxf(lm1, al1);
            lm2 = fmaxf(lm2, al2); lm3 = fmaxf(lm3, al3);
        }
    }
    if (lane == 0) { wmax[w][0] = lm0; wmax[w][1] = lm1; wmax[w][2] = lm2; wmax[w][3] = lm3; }
    __syncthreads();
    if (t < 4) {
        float m = -3.4e38f;
        for (int ww = 0; ww < 8; ww++) m = fmaxf(m, wmax[ww][t]);
        hmax[t] = m;
    }
    __syncthreads();

    /* pass 1.5: exp + den */
    for (int t2 = t; t2 < deg * 4; t2 += 256) {
        int slot = beg + (t2 >> 2);
        int h    = t2 & 3;
        float ex = __expf(g_ex[(size_t)slot * 4 + h] - hmax[h]);
        g_ex[(size_t)slot * 4 + h] = ex;
        atomicAdd(&den[h], ex);
    }
    __syncthreads();

    /* pass 2: aggregate v, edge-attr moments, degree-norm branch */
    int   h0 = t >> 7, h1 = h0 + 2, hT = t >> 6;
    float agg0 = 0.f, agg1 = 0.f, Tc = 0.f, xwc = 0.f;
    float ddis = g_dis[d];
    for (int j = 0; j < deg; j++) {
        int slot = beg + j;
        int e    = g_eid[slot];
        int row  = g_ero[slot];
        float e0 = g_ex[(size_t)slot * 4 + h0];
        float e1 = g_ex[(size_t)slot * 4 + h1];
        float eT = g_ex[(size_t)slot * 4 + hT];
        const float* vr = g_qkvo + VOFF + (size_t)row * 512;
        agg0 += e0 * vr[t];
        agg1 += e1 * vr[256 + t];
        Tc   += eT * ea[(size_t)e * 64 + (t & 63)];
        if (t < 128)
            xwc += ddis * g_ewc[e] * g_dis[row] * g_xl[(size_t)row * 128 + t];
    }
    if (t < 128) sxw[t] = xwc;
    __syncthreads();

    float d0 = den[h0] + 1e-16f, d1 = den[h1] + 1e-16f, dT = den[hT] + 1e-16f;
    float s0 = den[h0] / d0,     s1 = den[h1] / d1;
    float xw = sxw[t & 127];
    g_qkvo[OOFF + (size_t)d * 512 + t]       += agg0 / d0 + s0 * ebias[t]       + xw;
    g_qkvo[OOFF + (size_t)d * 512 + 256 + t] += agg1 / d1 + s1 * ebias[256 + t] + xw;
    g_T[(size_t)d * 256 + t]                  = Tc / dT;
}

/* ------------------------------------------------------------------ */
/* BatchNorm                                                            */
/* ------------------------------------------------------------------ */
__global__ void bnzero()
{
    int c = threadIdx.x;
    g_bns[c] = 0.f; g_bnq[c] = 0.f;
}

__global__ void bnstat(int n)
{
    int c  = threadIdx.x;
    int r0 = blockIdx.x * 128;
    float s = 0.f, q = 0.f;
    for (int r = 0; r < 128; r++) {
        float v = g_h1[(size_t)(r0 + r) * 128 + c];
        s += v; q += v * v;
    }
    atomicAdd(&g_bns[c], s);
    atomicAdd(&g_bnq[c], q);
}

__global__ void bnfin(const float* __restrict__ g, const float* __restrict__ b, int n)
{
    int c = threadIdx.x;
    float mu  = g_bns[c] / (float)n;
    float var = g_bnq[c] / (float)n - mu * mu;
    float sc  = g[c] * rsqrtf(var + 1e-5f);
    g_bsc[c] = sc;
    g_bsh[c] = b[c] - mu * sc;
}

__global__ void bnapply(float* __restrict__ out, int n)
{
    int i = blockIdx.x * 256 + threadIdx.x;
    if (i < n * 128) {
        int c = i & 127;
        out[i] = g_h1[i] * g_bsc[c] + g_bsh[c];
    }
}

/* ------------------------------------------------------------------ */
/* Top-k pooling                                                        */
/* ------------------------------------------------------------------ */
__global__ void wnorm_k(const float* __restrict__ w)
{
    __shared__ float s[128];
    int t = threadIdx.x;
    s[t] = w[t] * w[t];
    __syncthreads();
    for (int o = 64; o; o >>= 1) {
        if (t < o) s[t] += s[t + o];
        __syncthreads();
    }
    if (t == 0) g_wn[0] = sqrtf(s[0]) + 1e-16f;
}

__global__ void score_k(const float* __restrict__ h, const float* __restrict__ w, int n)
{
    int warp = (blockIdx.x * blockDim.x + threadIdx.x) >> 5;
    int lane = threadIdx.x & 31;
    if (warp >= n) return;
    float a = 0.f;
    const float* hr = h + (size_t)warp * 128;
    for (int c = lane; c < 128; c += 32) a += hr[c] * w[c];
#pragma unroll
    for (int o = 16; o; o >>= 1) a += __shfl_xor_sync(~0u, a, o);
    if (lane == 0) g_sc[warp] = tanhf(a / g_wn[0]);
}

__global__ void nidinit(int n)
{
    int i = blockIdx.x * 256 + threadIdx.x;
    if (i < n) g_nid[i] = -1;
}

/* one block per graph; threads == n_per (pow2 <= 1024). Bitonic sort:
   descending by value, ascending index on ties (matches jax top_k). */
__global__ void topk_pool(int n_per, int kk)
{
    __shared__ float sv[1024];
    __shared__ int   si[1024];
    int b = blockIdx.x, t = threadIdx.x;
    sv[t] = g_sc[b * n_per + t];
    si[t] = t;
    __syncthreads();
    for (int k2 = 2; k2 <= n_per; k2 <<= 1) {
        for (int j = k2 >> 1; j > 0; j >>= 1) {
            int ixj = t ^ j;
            if (ixj > t) {
                bool up = ((t & k2) == 0);
                float va = sv[t], vb = sv[ixj];
                int   ia = si[t], ib = si[ixj];
                bool aFirst = (va > vb) || (va == vb && ia < ib);
                if (up ? !aFirst : aFirst) {
                    sv[t] = vb; sv[ixj] = va;
                    si[t] = ib; si[ixj] = ia;
                }
            }
            __syncthreads();
        }
    }
    if (t < kk) {
        int gi = b * n_per + si[t];
        int r  = b * kk + t;
        g_vals[r] = sv[t];
        g_perm[r] = gi;
        g_nid[gi] = r;
    }
}

__global__ void gather_k(const float* __restrict__ hin, float* __restrict__ hout, int n_new)
{
    int i = blockIdx.x * 256 + threadIdx.x;
    if (i < n_new * 128) {
        int r = i >> 7, c = i & 127;
        hout[i] = hin[(size_t)g_perm[r] * 128 + c] * g_vals[r];
    }
}

__global__ void remap_k()
{
    int e = blockIdx.x * 256 + threadIdx.x;
    if (e < ETOT && g_keep[e]) {
        int nr = g_nid[g_row[e]], nc = g_nid[g_col[e]];
        if (nr >= 0 && nc >= 0) { g_row[e] = nr; g_col[e] = nc; }
        else { g_keep[e] = 0; g_row[e] = 0; g_col[e] = 0; g_ewc[e] = 0.f; }
    }
}

__global__ void reps_k(const float* __restrict__ h, int n_per, int which)
{
    int b = blockIdx.x, c = threadIdx.x;
    float mx = -3.4e38f, sm = 0.f;
    for (int r = 0; r < n_per; r++) {
        float v = h[(size_t)(b * n_per + r) * 128 + c];
        mx = fmaxf(mx, v);
        sm += v;
    }
    float* rep = which ? g_rep1 : g_rep0;
    rep[b * 256 + c]       = mx;
    rep[b * 256 + 128 + c] = sm / (float)n_per;
}

__global__ void add_rep(float* __restrict__ out)
{
    int i = blockIdx.x * 256 + threadIdx.x;
    if (i < BGR * 256) out[i] = g_rep0[i] + g_rep1[i];
}

/* ------------------------------------------------------------------ */
/* Host orchestration                                                   */
/* ------------------------------------------------------------------ */
extern "C" void kernel_launch(void* const* d_in, const int* in_sizes, int n_in,
                              void* d_out, int out_size)
{
    const float* x        = (const float*)d_in[0];
    const float* ea       = (const float*)d_in[1];
    const int*   ei       = (const int*)  d_in[2];
    const float* ew_in    = (const float*)d_in[3];
    const float* lin0_w   = (const float*)d_in[5];
    const float* lin0_b   = (const float*)d_in[6];
    const float* lin_w    = (const float*)d_in[7];
    const float* lin_b    = (const float*)d_in[8];
    const float* q_w      = (const float*)d_in[9];
    const float* q_b      = (const float*)d_in[10];
    const float* k_w      = (const float*)d_in[11];
    const float* k_b      = (const float*)d_in[12];
    const float* v_w      = (const float*)d_in[13];
    const float* v_b      = (const float*)d_in[14];
    const float* e_w      = (const float*)d_in[15];
    const float* e_b      = (const float*)d_in[16];
    const float* s_w      = (const float*)d_in[17];
    const float* s_b      = (const float*)d_in[18];
    const float* tr_w     = (const float*)d_in[19];
    const float* tr_b     = (const float*)d_in[20];
    const float* bn_g     = (const float*)d_in[21];
    const float* bn_b     = (const float*)d_in[22];
    const float* pool_w   = (const float*)d_in[23];
    float*       out      = (float*)d_out;

    float *p_xl, *p_qkvo, *p_P, *p_T, *p_h1, *p_hA, *p_hB, *p_wcat, *p_bcat, *p_wp, *p_bp;
    cudaGetSymbolAddress((void**)&p_xl,   g_xl);
    cudaGetSymbolAddress((void**)&p_qkvo, g_qkvo);
    cudaGetSymbolAddress((void**)&p_P,    g_P);
    cudaGetSymbolAddress((void**)&p_T,    g_T);
    cudaGetSymbolAddress((void**)&p_h1,   g_h1);
    cudaGetSymbolAddress((void**)&p_hA,   g_hA);
    cudaGetSymbolAddress((void**)&p_hB,   g_hB);
    cudaGetSymbolAddress((void**)&p_wcat, g_wcat);
    cudaGetSymbolAddress((void**)&p_bcat, g_bcat);
    cudaGetSymbolAddress((void**)&p_wp,   g_wp);
    cudaGetSymbolAddress((void**)&p_bp,   g_bp);

    float* p_o = p_qkvo + OOFF;

    const int EB = (ETOT + 255) / 256;

    /* edge state init (must run every call: graph replays mutate it) */
    einit<<<EB, 256>>>(ei, ew_in);

    auto build_csr = [&](int n)
    {
        zero3<<<(n + 255) / 256, 256>>>(n);
        degcnt<<<EB, 256>>>();
        disk<<<(n + 255) / 256, 256>>>(n);
        scan_excl<<<1, 1024>>>(n);
        fillk<<<EB, 256>>>();
    };

    auto run_layer = [&](const float* hin, int inF, int n,
                         const float* lw, const float* lb, int L, float* hout)
    {
        const float* qw  = q_w  + (size_t)L * 128 * 512;
        const float* qb  = q_b  + (size_t)L * 512;
        const float* kw  = k_w  + (size_t)L * 128 * 512;
        const float* kb  = k_b  + (size_t)L * 512;
        const float* vw  = v_w  + (size_t)L * 128 * 512;
        const float* vb  = v_b  + (size_t)L * 512;
        const float* eww = e_w  + (size_t)L * 64 * 512;
        const float* ebb = e_b  + (size_t)L * 512;
        const float* sw  = s_w  + (size_t)L * 128 * 512;
        const float* sb  = s_b  + (size_t)L * 512;
        const float* trw = tr_w + (size_t)L * 512 * 128;
        const float* trb = tr_b + (size_t)L * 128;
        const float* bg  = bn_g + (size_t)L * 128;
        const float* bb  = bn_b + (size_t)L * 128;

        int mb = n / 128;

        /* weight prep */
        catqkvs<<<1024, 256>>>(qw, kw, vw, sw, qb, kb, vb, sb);
        wpbp_build<<<4128, 256>>>(qw, qb, eww);

        /* xl = hin @ lw + lb */
        tgemm<<<dim3(1, mb), 256>>>(hin, inF, 0, lw, 128, 0, lb, 0,
                                    p_xl, 128, 0, inF, 0);
        /* fused q|k|v|skip : z = 4 */
        tgemm<<<dim3(4, mb, 4), 256>>>(p_xl, 128, 0, p_wcat, 512, 65536,
                                       p_bcat, 512,
                                       p_qkvo, 512, (long)NMAX * 512, 128, 0);
        /* P = xl @ W_P + b_P */
        tgemm<<<dim3(2, mb), 256>>>(p_xl, 128, 0, p_wp, 256, 0, p_bp, 0,
                                    p_P, 256, 0, 128, 0);

        /* attention + aggregation */
        node_kernel<<<n, 256>>>(ea, ebb);

        /* out += T @ e_w (block-diag per head) — 4 heads in grid.z */
        tgemm<<<dim3(1, mb, 4), 256>>>(p_T, 256, 64, eww, 512, 128, nullptr, 0,
                                       p_o, 512, 128, 64, 2);

        /* h1 = relu(out @ tr_w + tr_b) ; bn */
        tgemm<<<dim3(1, mb), 256>>>(p_o, 512, 0, trw, 128, 0, trb, 0,
                                    p_h1, 128, 0, 512, 1);
        bnzero<<<1, 128>>>();
        bnstat<<<n / 128, 128>>>(n);
        bnfin<<<1, 128>>>(bg, bb, n);
        bnapply<<<(n * 128 + 255) / 256, 256>>>(hout, n);
    };

    auto do_pool = [&](const float* hin, float* hout, int n_old, int n_per,
                       const float* w, int which)
    {
        int kk    = n_per / 2;
        int n_new = BGR * kk;
        wnorm_k<<<1, 128>>>(w);
        score_k<<<n_old / 8, 256>>>(hin, w, n_old);
        nidinit<<<(n_old + 255) / 256, 256>>>(n_old);
        topk_pool<<<BGR, n_per>>>(n_per, kk);
        gather_k<<<(n_new * 128 + 255) / 256, 256>>>(hin, hout, n_new);
        remap_k<<<EB, 256>>>();
        reps_k<<<BGR, 128>>>(hout, kk, which);
    };

    /* graph epoch 1: layers 0,1 share the full edge set */
    build_csr(32768);
    run_layer(x, 256, 32768, lin0_w, lin0_b, 0, p_hA);
    run_layer(p_hA, 128, 32768, lin_w + 0 * 128 * 128, lin_b + 0 * 128, 1, p_hB);
    do_pool(p_hB, p_hA, 32768, 1024, pool_w, 0);

    /* graph epoch 2: layers 2,3 share the post-pool edge set */
    build_csr(16384);
    run_layer(p_hA, 128, 16384, lin_w + 1 * 128 * 128, lin_b + 1 * 128, 2, p_hB);
    run_layer(p_hB, 128, 16384, lin_w + 2 * 128 * 128, lin_b + 2 * 128, 3, p_hA);
    do_pool(p_hA, p_hB, 16384, 512, pool_w + 128, 1);

    add_rep<<<32, 256>>>(out);
}